// round 14
// baseline (speedup 1.0000x reference)
#include <cuda_runtime.h>
#include <cuda_fp16.h>
#include <math.h>
#include <stdint.h>

#define B_   16
#define C_   1536
#define N_   1024
#define M_   64
#define L_   128
#define G_   256
#define HID_ 512

// ---------------- scratch (device globals) ----------------
static __device__ __half g_Xh[B_ * C_ * N_];      // x fp16
static __device__ __half g_Wh[1024 * C_];         // W1 fp16 (rows 0..511 Wc1, 512..1023 Ws1)
static __device__ __half g_W2h[192 * HID_];       // W2 fp16 (rows 0..127 Wc2, 128..191 Ws2)
static __device__ __half g_Hh[B_ * 1024 * N_];    // hidden fp16 (relu'd)
static __device__ __half g_Fh[B_ * L_ * N_];      // f fp16
static __device__ float g_P   [B_ * M_ * N_];
static __device__ float g_T   [B_ * N_];
static __device__ float g_RN  [B_ * N_];
static __device__ float g_D   [B_ * N_];
static __device__ float g_tok [B_ * G_];
static __device__ float g_aggp[B_ * 8 * L_ * M_];

// ---------------- PTX helpers ----------------
__device__ __forceinline__ void ldm_x4(uint32_t &r0, uint32_t &r1, uint32_t &r2, uint32_t &r3, uint32_t addr) {
    asm volatile("ldmatrix.sync.aligned.m8n8.x4.shared.b16 {%0,%1,%2,%3}, [%4];"
                 : "=r"(r0), "=r"(r1), "=r"(r2), "=r"(r3) : "r"(addr));
}
__device__ __forceinline__ void ldm_x4t(uint32_t &r0, uint32_t &r1, uint32_t &r2, uint32_t &r3, uint32_t addr) {
    asm volatile("ldmatrix.sync.aligned.m8n8.x4.trans.shared.b16 {%0,%1,%2,%3}, [%4];"
                 : "=r"(r0), "=r"(r1), "=r"(r2), "=r"(r3) : "r"(addr));
}
__device__ __forceinline__ void mma16816h(float* c, const uint32_t* a, const uint32_t* b) {
    asm volatile("mma.sync.aligned.m16n8k16.row.col.f32.f16.f16.f32 "
                 "{%0,%1,%2,%3},{%4,%5,%6,%7},{%8,%9},{%0,%1,%2,%3};"
                 : "+f"(c[0]), "+f"(c[1]), "+f"(c[2]), "+f"(c[3])
                 : "r"(a[0]), "r"(a[1]), "r"(a[2]), "r"(a[3]), "r"(b[0]), "r"(b[1]));
}
__device__ __forceinline__ void cp16(uint32_t saddr, const void* gaddr) {
    asm volatile("cp.async.cg.shared.global [%0], [%1], 16;" :: "r"(saddr), "l"(gaddr));
}
#define CP_COMMIT() asm volatile("cp.async.commit_group;")
#define CP_WAIT(n)  asm volatile("cp.async.wait_group %0;" :: "n"(n))

__device__ __forceinline__ uint32_t smem_u32(const void* p) {
    uint32_t a;
    asm("{ .reg .u64 t; cvta.to.shared.u64 t, %1; cvt.u32.u64 %0, t; }" : "=r"(a) : "l"(p));
    return a;
}
__device__ __forceinline__ float tanh_fast(float x) {
    float r;
    asm("tanh.approx.f32 %0, %1;" : "=f"(r) : "f"(x));
    return r;
}

// ---------------- split X: fp32 -> fp16 ----------------
__global__ void k_splitX(const float* __restrict__ src, int n4)
{
    for (int i = blockIdx.x * blockDim.x + threadIdx.x; i < n4; i += gridDim.x * blockDim.x) {
        float4 v = reinterpret_cast<const float4*>(src)[i];
        __half2 ph0 = __halves2half2(__float2half_rn(v.x), __float2half_rn(v.y));
        __half2 ph1 = __halves2half2(__float2half_rn(v.z), __float2half_rn(v.w));
        uint2 uh = {*reinterpret_cast<uint32_t*>(&ph0), *reinterpret_cast<uint32_t*>(&ph1)};
        *reinterpret_cast<uint2*>(g_Xh + (size_t)i * 4) = uh;
    }
}

// ---------------- split ALL weights in one launch ----------------
// ranges (in float4 units): [0, r1) Wc1 -> g_Wh; [r1, r2) Ws1 -> g_Wh+off;
//                           [r2, r3) Wc2 -> g_W2h; [r3, r4) Ws2 -> g_W2h+off
__global__ void k_splitW(const float* __restrict__ Wc1, const float* __restrict__ Ws1,
                         const float* __restrict__ Wc2, const float* __restrict__ Ws2)
{
    const int r1 = (HID_ * C_) / 4;            // 196608
    const int r2 = r1 + (HID_ * C_) / 4;       // 393216
    const int r3 = r2 + (L_ * HID_) / 4;       // +16384
    const int r4 = r3 + (M_ * HID_) / 4;       // +8192
    for (int i = blockIdx.x * blockDim.x + threadIdx.x; i < r4; i += gridDim.x * blockDim.x) {
        const float* s;
        __half* d;
        int j;
        if (i < r1)      { s = Wc1; d = g_Wh;                       j = i; }
        else if (i < r2) { s = Ws1; d = g_Wh + (size_t)HID_ * C_;   j = i - r1; }
        else if (i < r3) { s = Wc2; d = g_W2h;                      j = i - r2; }
        else             { s = Ws2; d = g_W2h + (size_t)L_ * HID_;  j = i - r3; }
        float4 v = reinterpret_cast<const float4*>(s)[j];
        __half2 ph0 = __halves2half2(__float2half_rn(v.x), __float2half_rn(v.y));
        __half2 ph1 = __halves2half2(__float2half_rn(v.z), __float2half_rn(v.w));
        uint2 uh = {*reinterpret_cast<uint32_t*>(&ph0), *reinterpret_cast<uint32_t*>(&ph1)};
        *reinterpret_cast<uint2*>(d + (size_t)j * 4) = uh;
    }
}

// ---------------- big GEMM (pure fp16 HMMA): h = relu(W*x + b) ----------------
#define HSTG 32768u

__global__ __launch_bounds__(256, 2) void k_hidden_mma(
    const float* __restrict__ bc1, const float* __restrict__ bs1)
{
    extern __shared__ __align__(128) char dsm[];
    const uint32_t sb = smem_u32(dsm);
    const int t = threadIdx.x, w = t >> 5, lane = t & 31;
    const int wm = (w >> 2) * 64, wn = (w & 3) * 32;
    const int g = lane >> 2, tg = lane & 3;
    const int b = blockIdx.z, m0 = blockIdx.y * 128, n0 = blockIdx.x * 128;

    const __half* gWh = g_Wh + (size_t)m0 * C_;
    const __half* gXh = g_Xh + (size_t)b * C_ * N_ + n0;

    uint32_t a_so[4], b_so[4];
    size_t   a_go[4], b_go[4];
#pragma unroll
    for (int p = 0; p < 4; p++) {
        int id = t + p * 256;
        int am = id >> 3, ac = id & 7;
        a_so[p] = (uint32_t)(am * 128 + ((ac ^ (am & 7)) << 4));
        a_go[p] = (size_t)am * C_ + ac * 8;
        int bk = id >> 4, bc = id & 15;
        b_so[p] = 16384u + (uint32_t)(bk * 256 + ((bc ^ (bk & 7)) << 4));
        b_go[p] = (size_t)bk * N_ + bc * 8;
    }

    auto load_A = [&](uint32_t sd, int k0) {
#pragma unroll
        for (int p = 0; p < 4; p++) cp16(sd + a_so[p], gWh + k0 + a_go[p]);
    };
    auto load_B = [&](uint32_t sd, int k0) {
#pragma unroll
        for (int p = 0; p < 4; p++) cp16(sd + b_so[p], gXh + (size_t)k0 * N_ + b_go[p]);
        CP_COMMIT();
    };

    const int r15 = lane & 15, sel = lane >> 4;
    uint32_t aoff0[4], bb0[2];
#pragma unroll
    for (int mt = 0; mt < 4; mt++) {
        int m = wm + mt * 16 + r15;
        aoff0[mt] = (uint32_t)(m * 128 + ((sel ^ (m & 7)) << 4));
    }
#pragma unroll
    for (int pp = 0; pp < 2; pp++) {
        int cn = (w & 3) * 4 + 2 * pp + sel;
        bb0[pp] = 16384u + (uint32_t)(r15 * 256 + ((cn ^ (r15 & 7)) << 4));
    }

    float acc[4][4][4];
#pragma unroll
    for (int i = 0; i < 4; i++)
#pragma unroll
        for (int j = 0; j < 4; j++)
#pragma unroll
            for (int q = 0; q < 4; q++) acc[i][j][q] = 0.f;

    load_A(sb, 0);          load_B(sb, 0);
    load_A(sb + HSTG, 64);  load_B(sb + HSTG, 64);

    const int NIT = C_ / 64;   // 24
    for (int it = 0; it < NIT; it++) {
        if (it + 2 < NIT) { CP_WAIT(1); } else { CP_WAIT(0); }
        __syncthreads();
        const uint32_t sd = sb + (uint32_t)(it % 3) * HSTG;

#pragma unroll
        for (int s = 0; s < 4; s++) {
            uint32_t ah[4][4], bh[4][2];
            const uint32_t axr = (uint32_t)(s << 5);
            const uint32_t bof = (uint32_t)(s << 12);
#pragma unroll
            for (int mt = 0; mt < 4; mt++)
                ldm_x4(ah[mt][0], ah[mt][1], ah[mt][2], ah[mt][3], sd + (aoff0[mt] ^ axr));
#pragma unroll
            for (int pp = 0; pp < 2; pp++)
                ldm_x4t(bh[2 * pp][0], bh[2 * pp][1], bh[2 * pp + 1][0], bh[2 * pp + 1][1],
                        sd + bb0[pp] + bof);
            if (it + 2 < NIT) {
                if (s == 0) load_A(sb + (uint32_t)((it + 2) % 3) * HSTG, (it + 2) * 64);
                if (s == 1) load_B(sb + (uint32_t)((it + 2) % 3) * HSTG, (it + 2) * 64);
            }
#pragma unroll
            for (int mt = 0; mt < 4; mt++)
#pragma unroll
                for (int nt = 0; nt < 4; nt++)
                    mma16816h(acc[mt][nt], ah[mt], bh[nt]);
        }
    }

    const float* bptr = (m0 >= HID_) ? (bs1 - HID_) : bc1;
    __half* OH = g_Hh + (size_t)b * 1024 * N_;
#pragma unroll
    for (int mt = 0; mt < 4; mt++) {
        const int m = m0 + wm + mt * 16 + g;
        const float bv0 = bptr[m];
        const float bv1 = bptr[m + 8];
#pragma unroll
        for (int nt = 0; nt < 4; nt++) {
            const int n = n0 + wn + nt * 8 + 2 * tg;
#pragma unroll
            for (int rr = 0; rr < 2; rr++) {
                const int mm = m + rr * 8;
                const float bvv = rr ? bv1 : bv0;
                float v0 = fmaxf(acc[mt][nt][rr * 2 + 0] + bvv, 0.f);
                float v1 = fmaxf(acc[mt][nt][rr * 2 + 1] + bvv, 0.f);
                __half2 ph = __halves2half2(__float2half_rn(v0), __float2half_rn(v1));
                *reinterpret_cast<__half2*>(OH + (size_t)mm * N_ + n) = ph;
            }
        }
    }
}

// ---------------- second-layer GEMM (pure fp16 HMMA): f and p ----------------
#define G2STG 12288u

__global__ __launch_bounds__(128, 1) void k_gemm2_mma(
    const float* __restrict__ bc2, const float* __restrict__ bs2)
{
    extern __shared__ __align__(128) char dsm2[];
    const uint32_t sb = smem_u32(dsm2);
    const int t = threadIdx.x, w = t >> 5, lane = t & 31;
    const int wn = w * 32;
    const int g = lane >> 2, tg = lane & 3;
    const int b = blockIdx.z, mblk = blockIdx.y, n0 = blockIdx.x * 128;
    const int m0 = mblk * 64;
    const int koff = (mblk == 2) ? 512 : 0;

    const __half* gAh = g_W2h + (size_t)m0 * HID_;
    const __half* gBh = g_Hh + ((size_t)b * 1024 + koff) * N_ + n0;

    const int amA = t >> 2, acA = t & 3;
    const uint32_t a_s0 = 16u * (uint32_t)(amA * 4 + (acA ^ ((amA >> 1) & 3)));
    const uint32_t a_s1 = 16u * (uint32_t)((amA + 32) * 4 + (acA ^ (((amA + 32) >> 1) & 3)));
    const size_t a_g0 = (size_t)amA * HID_ + acA * 8;
    const size_t a_g1 = (size_t)(amA + 32) * HID_ + acA * 8;
    const int bkB = t >> 4, bcB = t & 15;
    uint32_t b_sl[4];
    size_t   b_gl[4];
#pragma unroll
    for (int p = 0; p < 4; p++) {
        int k = bkB + p * 8;
        b_sl[p] = 16u * (uint32_t)(k * 16 + (bcB ^ (k & 7)));
        b_gl[p] = (size_t)k * N_ + bcB * 8;
    }

    auto load_stage = [&](uint32_t sd, int k0) {
        cp16(sd + a_s0, gAh + k0 + a_g0);
        cp16(sd + a_s1, gAh + k0 + a_g1);
        const size_t kk = (size_t)k0 * N_;
#pragma unroll
        for (int p = 0; p < 4; p++)
            cp16(sd + 4096u + b_sl[p], gBh + kk + b_gl[p]);
        CP_COMMIT();
    };

    const int r15 = lane & 15, sel = lane >> 4;
    uint32_t aoff[2][4], bb0[2][2];
#pragma unroll
    for (int s = 0; s < 2; s++) {
#pragma unroll
        for (int mt = 0; mt < 4; mt++) {
            int m = mt * 16 + r15;
            int c = 2 * s + sel;
            aoff[s][mt] = 16u * (uint32_t)(m * 4 + (c ^ ((m >> 1) & 3)));
        }
        int k = s * 16 + r15;
#pragma unroll
        for (int pp = 0; pp < 2; pp++) {
            int cn = w * 4 + 2 * pp + sel;
            bb0[s][pp] = 16u * (uint32_t)(k * 16 + (cn ^ (k & 7)));
        }
    }

    float acc[4][4][4];
#pragma unroll
    for (int i = 0; i < 4; i++)
#pragma unroll
        for (int j = 0; j < 4; j++)
#pragma unroll
            for (int q = 0; q < 4; q++) acc[i][j][q] = 0.f;

    load_stage(sb, 0);
    load_stage(sb + G2STG, 32);

    const int NIT = HID_ / 32;   // 16
    for (int it = 0; it < NIT; it++) {
        if (it + 2 < NIT) { CP_WAIT(1); } else { CP_WAIT(0); }
        __syncthreads();
        const uint32_t sd = sb + (uint32_t)(it % 3) * G2STG;

#pragma unroll
        for (int s = 0; s < 2; s++) {
            uint32_t ah[4][4], bh[4][2];
#pragma unroll
            for (int mt = 0; mt < 4; mt++)
                ldm_x4(ah[mt][0], ah[mt][1], ah[mt][2], ah[mt][3], sd + aoff[s][mt]);
#pragma unroll
            for (int pp = 0; pp < 2; pp++)
                ldm_x4t(bh[2 * pp][0], bh[2 * pp][1], bh[2 * pp + 1][0], bh[2 * pp + 1][1],
                        sd + 4096u + bb0[s][pp]);
            if (s == 0 && it + 2 < NIT)
                load_stage(sb + (uint32_t)((it + 2) % 3) * G2STG, (it + 2) * 32);
#pragma unroll
            for (int mt = 0; mt < 4; mt++)
#pragma unroll
                for (int nt = 0; nt < 4; nt++)
                    mma16816h(acc[mt][nt], ah[mt], bh[nt]);
        }
    }

#pragma unroll
    for (int mt = 0; mt < 4; mt++) {
#pragma unroll
        for (int rr = 0; rr < 2; rr++) {
            const int gm = m0 + mt * 16 + g + rr * 8;
            const float bv = (gm < 128) ? bc2[gm] : bs2[gm - 128];
#pragma unroll
            for (int nt = 0; nt < 4; nt++) {
                const int n = n0 + wn + nt * 8 + 2 * tg;
                float v0 = acc[mt][nt][rr * 2 + 0] + bv;
                float v1 = acc[mt][nt][rr * 2 + 1] + bv;
                if (gm < 128) {
                    __half2 ph = __halves2half2(__float2half_rn(v0), __float2half_rn(v1));
                    *reinterpret_cast<__half2*>(g_Fh + (size_t)b * L_ * N_ + (size_t)gm * N_ + n) = ph;
                } else {
                    float2 v = {v0, v1};
                    *reinterpret_cast<float2*>(g_P + (size_t)b * M_ * N_ + (size_t)(gm - 128) * N_ + n) = v;
                }
            }
        }
    }
}

// ---------------- fused token MLP: tok = (relu(t@Wt1^T+bt1))@Wt2^T + bt2 ----------------
// one CTA per batch, 512 threads (16 warps). Phase 1: 512 outputs, warp-per-output x32.
// Phase 2: 256 outputs from smem ht.
__global__ __launch_bounds__(512) void k_tok(
    const float* __restrict__ t_in, const float* __restrict__ Wt1, const float* __restrict__ bt1,
    const float* __restrict__ Wt2, const float* __restrict__ bt2)
{
    __shared__ float ht[HID_];
    const int b = blockIdx.x;
    const int w = threadIdx.x >> 5, lane = threadIdx.x & 31;
    const float* v = t_in + (size_t)b * C_;

    for (int m = w; m < HID_; m += 16) {
        const float* a = Wt1 + (size_t)m * C_;
        float s = 0.f;
        for (int k = lane; k < C_; k += 32) s = fmaf(a[k], v[k], s);
#pragma unroll
        for (int o = 16; o; o >>= 1) s += __shfl_xor_sync(0xffffffffu, s, o);
        if (lane == 0) ht[m] = fmaxf(s + bt1[m], 0.f);
    }
    __syncthreads();
    for (int m = w; m < G_; m += 16) {
        const float* a = Wt2 + (size_t)m * HID_;
        float s = 0.f;
        for (int k = lane; k < HID_; k += 32) s = fmaf(a[k], ht[k], s);
#pragma unroll
        for (int o = 16; o; o >>= 1) s += __shfl_xor_sync(0xffffffffu, s, o);
        if (lane == 0) g_tok[b * G_ + m] = s + bt2[m];
    }
}

// ---------------- Sinkhorn OT (3 iters) + exp, in place on g_P ----------------
__global__ void k_sinkhorn(const float* __restrict__ dust)
{
    const int b = blockIdx.x;
    const int tid = threadIdx.x;
    const float alpha = *dust;
    const float nrm = -logf((float)(M_ + N_));
    __shared__ float u[M_ + 1];
    __shared__ float v[N_];
    float* S = g_P + (size_t)b * M_ * N_;
    v[tid] = 0.f;
    __syncthreads();
    const int warp = tid >> 5, lane = tid & 31;

    for (int it = 0; it < 3; it++) {
        for (int r = warp; r <= M_; r += 32) {
            float mx = -3.4e38f;
            if (r < M_) { for (int n = lane; n < N_; n += 32) mx = fmaxf(mx, S[r * N_ + n] + v[n]); }
            else        { for (int n = lane; n < N_; n += 32) mx = fmaxf(mx, alpha + v[n]); }
#pragma unroll
            for (int o = 16; o; o >>= 1) mx = fmaxf(mx, __shfl_xor_sync(0xffffffffu, mx, o));
            float s = 0.f;
            if (r < M_) { for (int n = lane; n < N_; n += 32) s += __expf(S[r * N_ + n] + v[n] - mx); }
            else        { for (int n = lane; n < N_; n += 32) s += __expf(alpha + v[n] - mx); }
#pragma unroll
            for (int o = 16; o; o >>= 1) s += __shfl_xor_sync(0xffffffffu, s, o);
            if (lane == 0) {
                float lmu = (r < M_) ? nrm : (__logf((float)N_) + nrm);
                u[r] = lmu - (mx + __logf(s));
            }
        }
        __syncthreads();
        {
            const int n = tid;
            float mx = alpha + u[M_];
            for (int r = 0; r < M_; r++) mx = fmaxf(mx, S[r * N_ + n] + u[r]);
            float s = __expf(alpha + u[M_] - mx);
            for (int r = 0; r < M_; r++) s += __expf(S[r * N_ + n] + u[r] - mx);
            v[n] = nrm - (mx + __logf(s));
        }
        __syncthreads();
    }
    for (int idx = tid; idx < M_ * N_; idx += 1024) {
        int r = idx >> 10, n = idx & (N_ - 1);
        S[idx] = __expf(S[idx] + u[r] + v[n] - nrm);
    }
}

// ---------------- per-pixel column norm of f + temperature T (fp16 f, smem Wtp) ----------------
__global__ void k_coln(const float* __restrict__ Wtp, const float* __restrict__ btp)
{
    __shared__ float sw[L_];
    if (threadIdx.x < L_) sw[threadIdx.x] = Wtp[threadIdx.x];
    __syncthreads();
    const int pid = blockIdx.x * blockDim.x + threadIdx.x;
    const int b = pid >> 10, n = pid & 1023;
    const __half* F = g_Fh + (size_t)b * L_ * N_ + n;
    float ss = 0.f, tp = 0.f;
#pragma unroll 4
    for (int l = 0; l < L_; l++) {
        float vv = __half2float(F[(size_t)l * N_]);
        ss = fmaf(vv, vv, ss);
        tp = fmaf(vv, sw[l], tp);
    }
    g_RN[pid] = 1.f / fmaxf(sqrtf(ss), 1e-12f);
    float xx = tp + *btp;
    g_T[pid] = __logf(1.f + __expf(-fabsf(xx))) + fmaxf(xx, 0.f);
}

// ---------------- burst (pure fp16 HMMA gram): fused sigmoid rowsum ----------------
__global__ __launch_bounds__(256, 2) void k_burst_mma(const float* __restrict__ bbp,
                                                      const float* __restrict__ bpp)
{
    extern __shared__ __align__(128) char dsmb[];
    const uint32_t sb = smem_u32(dsmb);
    __shared__ float rs[128][4];
    const int t = threadIdx.x, w = t >> 5, lane = t & 31;
    const int wm = (w >> 2) * 64, wn = (w & 3) * 32;
    const int g = lane >> 2, tg = lane & 3;
    const int b = blockIdx.y, i0 = blockIdx.x * 128;
    const float burst_b = *bbp, burst_p = *bpp;

    const __half* Fh = g_Fh + (size_t)b * L_ * N_;

    auto load_tile = [&](uint32_t dst, int col0) {
#pragma unroll
        for (int p = 0; p < 8; p++) {
            int id = t + p * 256;
            int row = id >> 4, c = id & 15;
            uint32_t off = (uint32_t)(row * 256 + ((c ^ (row & 7)) << 4));
            cp16(dst + off, Fh + (size_t)row * N_ + col0 + c * 8);
        }
        CP_COMMIT();
    };

    const int r15 = lane & 15, sel = lane >> 4;
    uint32_t aoffc[4], boffc[2];
#pragma unroll
    for (int mt = 0; mt < 4; mt++) {
        int cm = ((wm + mt * 16) >> 3) + sel;
        aoffc[mt] = (uint32_t)(r15 * 256 + ((cm ^ (r15 & 7)) << 4));
    }
#pragma unroll
    for (int pp = 0; pp < 2; pp++) {
        int cj = (wn >> 3) + 2 * pp + sel;
        boffc[pp] = (uint32_t)(r15 * 256 + ((cj ^ (r15 & 7)) << 4));
    }

    float rni[4][2], Tii[4][2];
#pragma unroll
    for (int mt = 0; mt < 4; mt++)
#pragma unroll
        for (int r = 0; r < 2; r++) {
            int gi = i0 + wm + mt * 16 + g + r * 8;
            rni[mt][r] = g_RN[b * N_ + gi];
            Tii[mt][r] = g_T [b * N_ + gi];
        }

    float rowp[4][2];
#pragma unroll
    for (int mt = 0; mt < 4; mt++) { rowp[mt][0] = 0.f; rowp[mt][1] = 0.f; }

    load_tile(sb, i0);
    load_tile(sb + 32768u, 0);

    for (int it = 0; it < 8; it++) {
        CP_WAIT(0);
        __syncthreads();
        const uint32_t fj = sb + 32768u + (uint32_t)(it & 1) * 32768u;

        float acc[4][4][4];
#pragma unroll
        for (int i = 0; i < 4; i++)
#pragma unroll
            for (int j = 0; j < 4; j++)
#pragma unroll
                for (int q = 0; q < 4; q++) acc[i][j][q] = 0.f;

#pragma unroll
        for (int kk = 0; kk < 8; kk++) {
            const uint32_t ka = (uint32_t)(kk * 4096);
            uint32_t ah[4][4], bh[4][2];
#pragma unroll
            for (int mt = 0; mt < 4; mt++)
                ldm_x4t(ah[mt][0], ah[mt][2], ah[mt][1], ah[mt][3], sb + ka + aoffc[mt]);
#pragma unroll
            for (int pp = 0; pp < 2; pp++)
                ldm_x4t(bh[2 * pp][0], bh[2 * pp][1], bh[2 * pp + 1][0], bh[2 * pp + 1][1],
                        fj + ka + boffc[pp]);
            if (kk == 0 && it + 1 < 8)
                load_tile(sb + 32768u + (uint32_t)((it + 1) & 1) * 32768u, (it + 1) * 128);
#pragma unroll
            for (int mt = 0; mt < 4; mt++)
#pragma unroll
                for (int nt = 0; nt < 4; nt++)
                    mma16816h(acc[mt][nt], ah[mt], bh[nt]);
        }

        const int j0 = it * 128;
#pragma unroll
        for (int nt = 0; nt < 4; nt++) {
            const int jc = j0 + wn + nt * 8 + 2 * tg;
            const float rn0 = g_RN[b * N_ + jc],     rn1 = g_RN[b * N_ + jc + 1];
            const float Tj0 = g_T [b * N_ + jc],     Tj1 = g_T [b * N_ + jc + 1];
#pragma unroll
            for (int mt = 0; mt < 4; mt++)
#pragma unroll
                for (int r = 0; r < 2; r++) {
                    float s0 = acc[mt][nt][r * 2 + 0] * rni[mt][r] * rn0;
                    float s1 = acc[mt][nt][r * 2 + 1] * rni[mt][r] * rn1;
                    float z0 = fmaf(0.5f * (Tii[mt][r] + Tj0), s0, burst_b);
                    float z1 = fmaf(0.5f * (Tii[mt][r] + Tj1), s1, burst_b);
                    rowp[mt][r] += fmaf(0.5f, tanh_fast(0.5f * z0), 0.5f);
                    rowp[mt][r] += fmaf(0.5f, tanh_fast(0.5f * z1), 0.5f);
                }
        }
    }

#pragma unroll
    for (int mt = 0; mt < 4; mt++)
#pragma unroll
        for (int r = 0; r < 2; r++) {
            float v = rowp[mt][r];
            v += __shfl_xor_sync(0xffffffffu, v, 1);
            v += __shfl_xor_sync(0xffffffffu, v, 2);
            if (tg == 0) rs[wm + mt * 16 + g + r * 8][w & 3] = v;
        }
    __syncthreads();
    if (t < 128) {
        float s = rs[t][0] + rs[t][1] + rs[t][2] + rs[t][3];
        float d = powf(s, burst_p);
        g_D[b * N_ + i0 + t] = fminf(fmaxf(d, 1e-3f), 1e3f);
    }
}

// ---------------- agg (split-K, deterministic; reads fp16 f) ----------------
__global__ __launch_bounds__(256) void k_agg(const float* __restrict__ lamp)
{
    const int b = blockIdx.y;
    const int part = blockIdx.x;
    const int nbase = part * 128;
    const float lam = 1.f / (1.f + __expf(-(*lamp)));
    const float oml = 1.f - lam;
    __shared__ float Ft[128][33];
    __shared__ float Pt[64][33];
    const int t = threadIdx.x, tx = t & 15, ty = t >> 4;
    const __half* F = g_Fh + (size_t)b * L_ * N_;
    const float* P = g_P + (size_t)b * M_ * N_;

    float acc[8][4];
#pragma unroll
    for (int i = 0; i < 8; i++)
#pragma unroll
        for (int j = 0; j < 4; j++) acc[i][j] = 0.f;

    for (int tl = 0; tl < 4; tl++) {
        const int n0 = nbase + tl * 32;
        __syncthreads();
#pragma unroll
        for (int p = 0; p < 16; p++) {
            int idx = t + p * 256; int row = idx >> 5, c = idx & 31;
            Ft[row][c] = __half2float(F[(size_t)row * N_ + n0 + c]);
        }
#pragma unroll
        for (int p = 0; p < 8; p++) {
            int idx = t + p * 256; int row = idx >> 5, c = idx & 31;
            float d = g_D[b * N_ + n0 + c];
            Pt[row][c] = P[(size_t)row * N_ + n0 + c] * (oml + lam / (d + 1e-6f));
        }
        __syncthreads();
#pragma unroll
        for (int n = 0; n < 32; n++) {
            float a[8], pv[4];
#pragma unroll
            for (int i = 0; i < 8; i++) a[i] = Ft[ty * 8 + i][n];
#pragma unroll
            for (int j = 0; j < 4; j++) pv[j] = Pt[tx * 4 + j][n];
#pragma unroll
            for (int i = 0; i < 8; i++)
#pragma unroll
                for (int j = 0; j < 4; j++) acc[i][j] = fmaf(a[i], pv[j], acc[i][j]);
        }
    }
    float* O = g_aggp + ((size_t)b * 8 + part) * L_ * M_;
#pragma unroll
    for (int i = 0; i < 8; i++)
#pragma unroll
        for (int j = 0; j < 4; j++)
            O[(ty * 8 + i) * M_ + tx * 4 + j] = acc[i][j];
}

// ---------------- final reduce + normalize + concat ----------------
__global__ void k_final(float* __restrict__ out)
{
    const int b = blockIdx.x, t = threadIdx.x;
    __shared__ float sAgg[L_ * M_];
    __shared__ float cn[64], cr[64], red[256];
    __shared__ float sh_tn, sh_gn;

    for (int idx = t; idx < L_ * M_; idx += 256) {
        float s = 0.f;
#pragma unroll
        for (int p = 0; p < 8; p++) s += g_aggp[((size_t)b * 8 + p) * L_ * M_ + idx];
        sAgg[idx] = s;
    }
    __syncthreads();

    if (t < 64) {
        float ss = 0.f;
        for (int l = 0; l < L_; l++) { float vv = sAgg[l * M_ + t]; ss = fmaf(vv, vv, ss); }
        float nn2 = fmaxf(sqrtf(ss), 1e-12f);
        cn[t] = nn2;
        cr[t] = ss / (nn2 * nn2);
    }
    float tv = g_tok[b * G_ + t];
    red[t] = tv * tv;
    __syncthreads();
    for (int o = 128; o; o >>= 1) { if (t < o) red[t] += red[t + o]; __syncthreads(); }
    float tokss = red[0];
    __syncthreads();
    red[t] = (t < 64) ? cr[t] : 0.f;
    __syncthreads();
    for (int o = 128; o; o >>= 1) { if (t < o) red[t] += red[t + o]; __syncthreads(); }
    if (t == 0) {
        float tn = fmaxf(sqrtf(tokss), 1e-12f);
        float gss = tokss / (tn * tn) + red[0];
        sh_tn = tn;
        sh_gn = fmaxf(sqrtf(gss), 1e-12f);
    }
    __syncthreads();

    const int ob = b * (G_ + L_ * M_);
    out[ob + t] = tv / (sh_tn * sh_gn);
    const float invg = 1.f / sh_gn;
    for (int idx = t; idx < L_ * M_; idx += 256) {
        int mcol = idx & (M_ - 1);
        out[ob + G_ + idx] = sAgg[idx] * invg / cn[mcol];
    }
}

// ---------------- launch ----------------
extern "C" void kernel_launch(void* const* d_in, const int* in_sizes, int n_in,
                              void* d_out, int out_size)
{
    const float* x    = (const float*)d_in[0];
    const float* tt   = (const float*)d_in[1];
    const float* Wt1  = (const float*)d_in[2];
    const float* bt1  = (const float*)d_in[3];
    const float* Wt2  = (const float*)d_in[4];
    const float* bt2  = (const float*)d_in[5];
    const float* Wc1  = (const float*)d_in[6];
    const float* bc1  = (const float*)d_in[7];
    const float* Wc2  = (const float*)d_in[8];
    const float* bc2  = (const float*)d_in[9];
    const float* Ws1  = (const float*)d_in[10];
    const float* bs1  = (const float*)d_in[11];
    const float* Ws2  = (const float*)d_in[12];
    const float* bs2  = (const float*)d_in[13];
    const float* Wtp  = (const float*)d_in[14];
    const float* btp  = (const float*)d_in[15];
    const float* dust = (const float*)d_in[16];
    const float* bb   = (const float*)d_in[17];
    const float* bp   = (const float*)d_in[18];
    const float* ld   = (const float*)d_in[19];
    float* out = (float*)d_out;

    cudaFuncSetAttribute(k_hidden_mma, cudaFuncAttributeMaxDynamicSharedMemorySize, 3 * HSTG);
    cudaFuncSetAttribute(k_gemm2_mma,  cudaFuncAttributeMaxDynamicSharedMemorySize, 3 * G2STG);
    cudaFuncSetAttribute(k_burst_mma,  cudaFuncAttributeMaxDynamicSharedMemorySize, 98304);

    k_splitX<<<1024, 256>>>(x, (B_ * C_ * N_) / 4);
    k_splitW<<<296, 256>>>(Wc1, Ws1, Wc2, Ws2);
    k_tok   <<<16, 512>>>(tt, Wt1, bt1, Wt2, bt2);

    k_hidden_mma<<<dim3(8, 8, 16), 256, 3 * HSTG>>>(bc1, bs1);
    k_gemm2_mma <<<dim3(8, 3, 16), 128, 3 * G2STG>>>(bc2, bs2);
    k_sinkhorn<<<16, 1024>>>(dust);
    k_coln    <<<64, 256>>>(Wtp, btp);
    k_burst_mma<<<dim3(8, 16), 256, 98304>>>(bb, bp);
    k_agg     <<<dim3(8, 16), 256>>>(ld);
    k_final   <<<16, 256>>>(out);
}

// round 16
// speedup vs baseline: 1.9415x; 1.9415x over previous
#include <cuda_runtime.h>
#include <cuda_fp16.h>
#include <math.h>
#include <stdint.h>

#define B_   16
#define C_   1536
#define N_   1024
#define M_   64
#define L_   128
#define G_   256
#define HID_ 512

// ---------------- scratch (device globals) ----------------
static __device__ __half g_Xh[B_ * C_ * N_];      // x fp16
static __device__ __half g_Wh[1024 * C_];         // W1 fp16 (rows 0..511 Wc1, 512..1023 Ws1)
static __device__ __half g_W2h[192 * HID_];       // W2 fp16 (rows 0..127 Wc2, 128..191 Ws2)
static __device__ __half g_Hh[B_ * 1024 * N_];    // hidden fp16 (relu'd)
static __device__ __half g_Fh[B_ * L_ * N_];      // f fp16
static __device__ float g_P   [B_ * M_ * N_];
static __device__ float g_T   [B_ * N_];
static __device__ float g_RN  [B_ * N_];
static __device__ float g_D   [B_ * N_];
static __device__ float g_Ht  [B_ * HID_];
static __device__ float g_tok [B_ * G_];
static __device__ float g_aggp[B_ * 8 * L_ * M_];

// ---------------- PTX helpers ----------------
__device__ __forceinline__ void ldm_x4(uint32_t &r0, uint32_t &r1, uint32_t &r2, uint32_t &r3, uint32_t addr) {
    asm volatile("ldmatrix.sync.aligned.m8n8.x4.shared.b16 {%0,%1,%2,%3}, [%4];"
                 : "=r"(r0), "=r"(r1), "=r"(r2), "=r"(r3) : "r"(addr));
}
__device__ __forceinline__ void ldm_x4t(uint32_t &r0, uint32_t &r1, uint32_t &r2, uint32_t &r3, uint32_t addr) {
    asm volatile("ldmatrix.sync.aligned.m8n8.x4.trans.shared.b16 {%0,%1,%2,%3}, [%4];"
                 : "=r"(r0), "=r"(r1), "=r"(r2), "=r"(r3) : "r"(addr));
}
__device__ __forceinline__ void mma16816h(float* c, const uint32_t* a, const uint32_t* b) {
    asm volatile("mma.sync.aligned.m16n8k16.row.col.f32.f16.f16.f32 "
                 "{%0,%1,%2,%3},{%4,%5,%6,%7},{%8,%9},{%0,%1,%2,%3};"
                 : "+f"(c[0]), "+f"(c[1]), "+f"(c[2]), "+f"(c[3])
                 : "r"(a[0]), "r"(a[1]), "r"(a[2]), "r"(a[3]), "r"(b[0]), "r"(b[1]));
}
__device__ __forceinline__ void cp16(uint32_t saddr, const void* gaddr) {
    asm volatile("cp.async.cg.shared.global [%0], [%1], 16;" :: "r"(saddr), "l"(gaddr));
}
#define CP_COMMIT() asm volatile("cp.async.commit_group;")
#define CP_WAIT(n)  asm volatile("cp.async.wait_group %0;" :: "n"(n))

__device__ __forceinline__ uint32_t smem_u32(const void* p) {
    uint32_t a;
    asm("{ .reg .u64 t; cvta.to.shared.u64 t, %1; cvt.u32.u64 %0, t; }" : "=r"(a) : "l"(p));
    return a;
}
__device__ __forceinline__ float tanh_fast(float x) {
    float r;
    asm("tanh.approx.f32 %0, %1;" : "=f"(r) : "f"(x));
    return r;
}

// ---------------- split X: fp32 -> fp16 ----------------
__global__ void k_splitX(const float* __restrict__ src, int n4)
{
    for (int i = blockIdx.x * blockDim.x + threadIdx.x; i < n4; i += gridDim.x * blockDim.x) {
        float4 v = reinterpret_cast<const float4*>(src)[i];
        __half2 ph0 = __halves2half2(__float2half_rn(v.x), __float2half_rn(v.y));
        __half2 ph1 = __halves2half2(__float2half_rn(v.z), __float2half_rn(v.w));
        uint2 uh = {*reinterpret_cast<uint32_t*>(&ph0), *reinterpret_cast<uint32_t*>(&ph1)};
        *reinterpret_cast<uint2*>(g_Xh + (size_t)i * 4) = uh;
    }
}

// ---------------- split ALL weights in one launch ----------------
__global__ void k_splitW(const float* __restrict__ Wc1, const float* __restrict__ Ws1,
                         const float* __restrict__ Wc2, const float* __restrict__ Ws2)
{
    const int r1 = (HID_ * C_) / 4;
    const int r2 = r1 + (HID_ * C_) / 4;
    const int r3 = r2 + (L_ * HID_) / 4;
    const int r4 = r3 + (M_ * HID_) / 4;
    for (int i = blockIdx.x * blockDim.x + threadIdx.x; i < r4; i += gridDim.x * blockDim.x) {
        const float* s;
        __half* d;
        int j;
        if (i < r1)      { s = Wc1; d = g_Wh;                       j = i; }
        else if (i < r2) { s = Ws1; d = g_Wh + (size_t)HID_ * C_;   j = i - r1; }
        else if (i < r3) { s = Wc2; d = g_W2h;                      j = i - r2; }
        else             { s = Ws2; d = g_W2h + (size_t)L_ * HID_;  j = i - r3; }
        float4 v = reinterpret_cast<const float4*>(s)[j];
        __half2 ph0 = __halves2half2(__float2half_rn(v.x), __float2half_rn(v.y));
        __half2 ph1 = __halves2half2(__float2half_rn(v.z), __float2half_rn(v.w));
        uint2 uh = {*reinterpret_cast<uint32_t*>(&ph0), *reinterpret_cast<uint32_t*>(&ph1)};
        *reinterpret_cast<uint2*>(d + (size_t)j * 4) = uh;
    }
}

// ---------------- big GEMM (pure fp16 HMMA): h = relu(W*x + b) ----------------
#define HSTG 32768u

__global__ __launch_bounds__(256, 2) void k_hidden_mma(
    const float* __restrict__ bc1, const float* __restrict__ bs1)
{
    extern __shared__ __align__(128) char dsm[];
    const uint32_t sb = smem_u32(dsm);
    const int t = threadIdx.x, w = t >> 5, lane = t & 31;
    const int wm = (w >> 2) * 64, wn = (w & 3) * 32;
    const int g = lane >> 2, tg = lane & 3;
    const int b = blockIdx.z, m0 = blockIdx.y * 128, n0 = blockIdx.x * 128;

    const __half* gWh = g_Wh + (size_t)m0 * C_;
    const __half* gXh = g_Xh + (size_t)b * C_ * N_ + n0;

    uint32_t a_so[4], b_so[4];
    size_t   a_go[4], b_go[4];
#pragma unroll
    for (int p = 0; p < 4; p++) {
        int id = t + p * 256;
        int am = id >> 3, ac = id & 7;
        a_so[p] = (uint32_t)(am * 128 + ((ac ^ (am & 7)) << 4));
        a_go[p] = (size_t)am * C_ + ac * 8;
        int bk = id >> 4, bc = id & 15;
        b_so[p] = 16384u + (uint32_t)(bk * 256 + ((bc ^ (bk & 7)) << 4));
        b_go[p] = (size_t)bk * N_ + bc * 8;
    }

    auto load_A = [&](uint32_t sd, int k0) {
#pragma unroll
        for (int p = 0; p < 4; p++) cp16(sd + a_so[p], gWh + k0 + a_go[p]);
    };
    auto load_B = [&](uint32_t sd, int k0) {
#pragma unroll
        for (int p = 0; p < 4; p++) cp16(sd + b_so[p], gXh + (size_t)k0 * N_ + b_go[p]);
        CP_COMMIT();
    };

    const int r15 = lane & 15, sel = lane >> 4;
    uint32_t aoff0[4], bb0[2];
#pragma unroll
    for (int mt = 0; mt < 4; mt++) {
        int m = wm + mt * 16 + r15;
        aoff0[mt] = (uint32_t)(m * 128 + ((sel ^ (m & 7)) << 4));
    }
#pragma unroll
    for (int pp = 0; pp < 2; pp++) {
        int cn = (w & 3) * 4 + 2 * pp + sel;
        bb0[pp] = 16384u + (uint32_t)(r15 * 256 + ((cn ^ (r15 & 7)) << 4));
    }

    float acc[4][4][4];
#pragma unroll
    for (int i = 0; i < 4; i++)
#pragma unroll
        for (int j = 0; j < 4; j++)
#pragma unroll
            for (int q = 0; q < 4; q++) acc[i][j][q] = 0.f;

    load_A(sb, 0);          load_B(sb, 0);
    load_A(sb + HSTG, 64);  load_B(sb + HSTG, 64);

    const int NIT = C_ / 64;   // 24
    for (int it = 0; it < NIT; it++) {
        if (it + 2 < NIT) { CP_WAIT(1); } else { CP_WAIT(0); }
        __syncthreads();
        const uint32_t sd = sb + (uint32_t)(it % 3) * HSTG;

#pragma unroll
        for (int s = 0; s < 4; s++) {
            uint32_t ah[4][4], bh[4][2];
            const uint32_t axr = (uint32_t)(s << 5);
            const uint32_t bof = (uint32_t)(s << 12);
#pragma unroll
            for (int mt = 0; mt < 4; mt++)
                ldm_x4(ah[mt][0], ah[mt][1], ah[mt][2], ah[mt][3], sd + (aoff0[mt] ^ axr));
#pragma unroll
            for (int pp = 0; pp < 2; pp++)
                ldm_x4t(bh[2 * pp][0], bh[2 * pp][1], bh[2 * pp + 1][0], bh[2 * pp + 1][1],
                        sd + bb0[pp] + bof);
            if (it + 2 < NIT) {
                if (s == 0) load_A(sb + (uint32_t)((it + 2) % 3) * HSTG, (it + 2) * 64);
                if (s == 1) load_B(sb + (uint32_t)((it + 2) % 3) * HSTG, (it + 2) * 64);
            }
#pragma unroll
            for (int mt = 0; mt < 4; mt++)
#pragma unroll
                for (int nt = 0; nt < 4; nt++)
                    mma16816h(acc[mt][nt], ah[mt], bh[nt]);
        }
    }

    const float* bptr = (m0 >= HID_) ? (bs1 - HID_) : bc1;
    __half* OH = g_Hh + (size_t)b * 1024 * N_;
#pragma unroll
    for (int mt = 0; mt < 4; mt++) {
        const int m = m0 + wm + mt * 16 + g;
        const float bv0 = bptr[m];
        const float bv1 = bptr[m + 8];
#pragma unroll
        for (int nt = 0; nt < 4; nt++) {
            const int n = n0 + wn + nt * 8 + 2 * tg;
#pragma unroll
            for (int rr = 0; rr < 2; rr++) {
                const int mm = m + rr * 8;
                const float bvv = rr ? bv1 : bv0;
                float v0 = fmaxf(acc[mt][nt][rr * 2 + 0] + bvv, 0.f);
                float v1 = fmaxf(acc[mt][nt][rr * 2 + 1] + bvv, 0.f);
                __half2 ph = __halves2half2(__float2half_rn(v0), __float2half_rn(v1));
                *reinterpret_cast<__half2*>(OH + (size_t)mm * N_ + n) = ph;
            }
        }
    }
}

// ---------------- second-layer GEMM (pure fp16 HMMA): f and p ----------------
#define G2STG 12288u

__global__ __launch_bounds__(128, 1) void k_gemm2_mma(
    const float* __restrict__ bc2, const float* __restrict__ bs2)
{
    extern __shared__ __align__(128) char dsm2[];
    const uint32_t sb = smem_u32(dsm2);
    const int t = threadIdx.x, w = t >> 5, lane = t & 31;
    const int wn = w * 32;
    const int g = lane >> 2, tg = lane & 3;
    const int b = blockIdx.z, mblk = blockIdx.y, n0 = blockIdx.x * 128;
    const int m0 = mblk * 64;
    const int koff = (mblk == 2) ? 512 : 0;

    const __half* gAh = g_W2h + (size_t)m0 * HID_;
    const __half* gBh = g_Hh + ((size_t)b * 1024 + koff) * N_ + n0;

    const int amA = t >> 2, acA = t & 3;
    const uint32_t a_s0 = 16u * (uint32_t)(amA * 4 + (acA ^ ((amA >> 1) & 3)));
    const uint32_t a_s1 = 16u * (uint32_t)((amA + 32) * 4 + (acA ^ (((amA + 32) >> 1) & 3)));
    const size_t a_g0 = (size_t)amA * HID_ + acA * 8;
    const size_t a_g1 = (size_t)(amA + 32) * HID_ + acA * 8;
    const int bkB = t >> 4, bcB = t & 15;
    uint32_t b_sl[4];
    size_t   b_gl[4];
#pragma unroll
    for (int p = 0; p < 4; p++) {
        int k = bkB + p * 8;
        b_sl[p] = 16u * (uint32_t)(k * 16 + (bcB ^ (k & 7)));
        b_gl[p] = (size_t)k * N_ + bcB * 8;
    }

    auto load_stage = [&](uint32_t sd, int k0) {
        cp16(sd + a_s0, gAh + k0 + a_g0);
        cp16(sd + a_s1, gAh + k0 + a_g1);
        const size_t kk = (size_t)k0 * N_;
#pragma unroll
        for (int p = 0; p < 4; p++)
            cp16(sd + 4096u + b_sl[p], gBh + kk + b_gl[p]);
        CP_COMMIT();
    };

    const int r15 = lane & 15, sel = lane >> 4;
    uint32_t aoff[2][4], bb0[2][2];
#pragma unroll
    for (int s = 0; s < 2; s++) {
#pragma unroll
        for (int mt = 0; mt < 4; mt++) {
            int m = mt * 16 + r15;
            int c = 2 * s + sel;
            aoff[s][mt] = 16u * (uint32_t)(m * 4 + (c ^ ((m >> 1) & 3)));
        }
        int k = s * 16 + r15;
#pragma unroll
        for (int pp = 0; pp < 2; pp++) {
            int cn = w * 4 + 2 * pp + sel;
            bb0[s][pp] = 16u * (uint32_t)(k * 16 + (cn ^ (k & 7)));
        }
    }

    float acc[4][4][4];
#pragma unroll
    for (int i = 0; i < 4; i++)
#pragma unroll
        for (int j = 0; j < 4; j++)
#pragma unroll
            for (int q = 0; q < 4; q++) acc[i][j][q] = 0.f;

    load_stage(sb, 0);
    load_stage(sb + G2STG, 32);

    const int NIT = HID_ / 32;   // 16
    for (int it = 0; it < NIT; it++) {
        if (it + 2 < NIT) { CP_WAIT(1); } else { CP_WAIT(0); }
        __syncthreads();
        const uint32_t sd = sb + (uint32_t)(it % 3) * G2STG;

#pragma unroll
        for (int s = 0; s < 2; s++) {
            uint32_t ah[4][4], bh[4][2];
#pragma unroll
            for (int mt = 0; mt < 4; mt++)
                ldm_x4(ah[mt][0], ah[mt][1], ah[mt][2], ah[mt][3], sd + aoff[s][mt]);
#pragma unroll
            for (int pp = 0; pp < 2; pp++)
                ldm_x4t(bh[2 * pp][0], bh[2 * pp][1], bh[2 * pp + 1][0], bh[2 * pp + 1][1],
                        sd + 4096u + bb0[s][pp]);
            if (s == 0 && it + 2 < NIT)
                load_stage(sb + (uint32_t)((it + 2) % 3) * G2STG, (it + 2) * 32);
#pragma unroll
            for (int mt = 0; mt < 4; mt++)
#pragma unroll
                for (int nt = 0; nt < 4; nt++)
                    mma16816h(acc[mt][nt], ah[mt], bh[nt]);
        }
    }

#pragma unroll
    for (int mt = 0; mt < 4; mt++) {
#pragma unroll
        for (int rr = 0; rr < 2; rr++) {
            const int gm = m0 + mt * 16 + g + rr * 8;
            const float bv = (gm < 128) ? bc2[gm] : bs2[gm - 128];
#pragma unroll
            for (int nt = 0; nt < 4; nt++) {
                const int n = n0 + wn + nt * 8 + 2 * tg;
                float v0 = acc[mt][nt][rr * 2 + 0] + bv;
                float v1 = acc[mt][nt][rr * 2 + 1] + bv;
                if (gm < 128) {
                    __half2 ph = __halves2half2(__float2half_rn(v0), __float2half_rn(v1));
                    *reinterpret_cast<__half2*>(g_Fh + (size_t)b * L_ * N_ + (size_t)gm * N_ + n) = ph;
                } else {
                    float2 v = {v0, v1};
                    *reinterpret_cast<float2*>(g_P + (size_t)b * M_ * N_ + (size_t)(gm - 128) * N_ + n) = v;
                }
            }
        }
    }
}

// ---------------- token MLP (reverted: warp-per-output, high parallelism) ----------------
__global__ void k_tok1(const float* __restrict__ t_in, const float* __restrict__ Wt1,
                       const float* __restrict__ bt1)
{
    const int b = blockIdx.x;
    const int w = threadIdx.x >> 5, lane = threadIdx.x & 31;
    const int m = blockIdx.y * 8 + w;
    const float* a = Wt1 + (size_t)m * C_;
    const float* v = t_in + (size_t)b * C_;
    float s = 0.f;
    for (int k = lane; k < C_; k += 32) s = fmaf(a[k], v[k], s);
#pragma unroll
    for (int o = 16; o; o >>= 1) s += __shfl_xor_sync(0xffffffffu, s, o);
    if (lane == 0) g_Ht[b * HID_ + m] = fmaxf(s + bt1[m], 0.f);
}

__global__ void k_tok2(const float* __restrict__ Wt2, const float* __restrict__ bt2)
{
    const int b = blockIdx.x;
    const int w = threadIdx.x >> 5, lane = threadIdx.x & 31;
    const int m = blockIdx.y * 8 + w;
    const float* a = Wt2 + (size_t)m * HID_;
    const float* v = g_Ht + (size_t)b * HID_;
    float s = 0.f;
    for (int k = lane; k < HID_; k += 32) s = fmaf(a[k], v[k], s);
#pragma unroll
    for (int o = 16; o; o >>= 1) s += __shfl_xor_sync(0xffffffffu, s, o);
    if (lane == 0) g_tok[b * G_ + m] = s + bt2[m];
}

// ---------------- Sinkhorn OT (3 iters) + exp, in place on g_P ----------------
__global__ void k_sinkhorn(const float* __restrict__ dust)
{
    const int b = blockIdx.x;
    const int tid = threadIdx.x;
    const float alpha = *dust;
    const float nrm = -logf((float)(M_ + N_));
    __shared__ float u[M_ + 1];
    __shared__ float v[N_];
    float* S = g_P + (size_t)b * M_ * N_;
    v[tid] = 0.f;
    __syncthreads();
    const int warp = tid >> 5, lane = tid & 31;

    for (int it = 0; it < 3; it++) {
        for (int r = warp; r <= M_; r += 32) {
            float mx = -3.4e38f;
            if (r < M_) { for (int n = lane; n < N_; n += 32) mx = fmaxf(mx, S[r * N_ + n] + v[n]); }
            else        { for (int n = lane; n < N_; n += 32) mx = fmaxf(mx, alpha + v[n]); }
#pragma unroll
            for (int o = 16; o; o >>= 1) mx = fmaxf(mx, __shfl_xor_sync(0xffffffffu, mx, o));
            float s = 0.f;
            if (r < M_) { for (int n = lane; n < N_; n += 32) s += __expf(S[r * N_ + n] + v[n] - mx); }
            else        { for (int n = lane; n < N_; n += 32) s += __expf(alpha + v[n] - mx); }
#pragma unroll
            for (int o = 16; o; o >>= 1) s += __shfl_xor_sync(0xffffffffu, s, o);
            if (lane == 0) {
                float lmu = (r < M_) ? nrm : (__logf((float)N_) + nrm);
                u[r] = lmu - (mx + __logf(s));
            }
        }
        __syncthreads();
        {
            const int n = tid;
            float mx = alpha + u[M_];
            for (int r = 0; r < M_; r++) mx = fmaxf(mx, S[r * N_ + n] + u[r]);
            float s = __expf(alpha + u[M_] - mx);
            for (int r = 0; r < M_; r++) s += __expf(S[r * N_ + n] + u[r] - mx);
            v[n] = nrm - (mx + __logf(s));
        }
        __syncthreads();
    }
    for (int idx = tid; idx < M_ * N_; idx += 1024) {
        int r = idx >> 10, n = idx & (N_ - 1);
        S[idx] = __expf(S[idx] + u[r] + v[n] - nrm);
    }
}

// ---------------- per-pixel column norm of f + temperature T ----------------
__global__ void k_coln(const float* __restrict__ Wtp, const float* __restrict__ btp)
{
    __shared__ float sw[L_];
    if (threadIdx.x < L_) sw[threadIdx.x] = Wtp[threadIdx.x];
    __syncthreads();
    const int pid = blockIdx.x * blockDim.x + threadIdx.x;
    const int b = pid >> 10, n = pid & 1023;
    const __half* F = g_Fh + (size_t)b * L_ * N_ + n;
    float ss = 0.f, tp = 0.f;
#pragma unroll 4
    for (int l = 0; l < L_; l++) {
        float vv = __half2float(F[(size_t)l * N_]);
        ss = fmaf(vv, vv, ss);
        tp = fmaf(vv, sw[l], tp);
    }
    g_RN[pid] = 1.f / fmaxf(sqrtf(ss), 1e-12f);
    float xx = tp + *btp;
    g_T[pid] = __logf(1.f + __expf(-fabsf(xx))) + fmaxf(xx, 0.f);
}

// ---------------- burst (pure fp16 HMMA gram): fused sigmoid rowsum ----------------
__global__ __launch_bounds__(256, 2) void k_burst_mma(const float* __restrict__ bbp,
                                                      const float* __restrict__ bpp)
{
    extern __shared__ __align__(128) char dsmb[];
    const uint32_t sb = smem_u32(dsmb);
    __shared__ float rs[128][4];
    const int t = threadIdx.x, w = t >> 5, lane = t & 31;
    const int wm = (w >> 2) * 64, wn = (w & 3) * 32;
    const int g = lane >> 2, tg = lane & 3;
    const int b = blockIdx.y, i0 = blockIdx.x * 128;
    const float burst_b = *bbp, burst_p = *bpp;

    const __half* Fh = g_Fh + (size_t)b * L_ * N_;

    auto load_tile = [&](uint32_t dst, int col0) {
#pragma unroll
        for (int p = 0; p < 8; p++) {
            int id = t + p * 256;
            int row = id >> 4, c = id & 15;
            uint32_t off = (uint32_t)(row * 256 + ((c ^ (row & 7)) << 4));
            cp16(dst + off, Fh + (size_t)row * N_ + col0 + c * 8);
        }
        CP_COMMIT();
    };

    const int r15 = lane & 15, sel = lane >> 4;
    uint32_t aoffc[4], boffc[2];
#pragma unroll
    for (int mt = 0; mt < 4; mt++) {
        int cm = ((wm + mt * 16) >> 3) + sel;
        aoffc[mt] = (uint32_t)(r15 * 256 + ((cm ^ (r15 & 7)) << 4));
    }
#pragma unroll
    for (int pp = 0; pp < 2; pp++) {
        int cj = (wn >> 3) + 2 * pp + sel;
        boffc[pp] = (uint32_t)(r15 * 256 + ((cj ^ (r15 & 7)) << 4));
    }

    float rni[4][2], Tii[4][2];
#pragma unroll
    for (int mt = 0; mt < 4; mt++)
#pragma unroll
        for (int r = 0; r < 2; r++) {
            int gi = i0 + wm + mt * 16 + g + r * 8;
            rni[mt][r] = g_RN[b * N_ + gi];
            Tii[mt][r] = g_T [b * N_ + gi];
        }

    float rowp[4][2];
#pragma unroll
    for (int mt = 0; mt < 4; mt++) { rowp[mt][0] = 0.f; rowp[mt][1] = 0.f; }

    load_tile(sb, i0);
    load_tile(sb + 32768u, 0);

    for (int it = 0; it < 8; it++) {
        CP_WAIT(0);
        __syncthreads();
        const uint32_t fj = sb + 32768u + (uint32_t)(it & 1) * 32768u;

        float acc[4][4][4];
#pragma unroll
        for (int i = 0; i < 4; i++)
#pragma unroll
            for (int j = 0; j < 4; j++)
#pragma unroll
                for (int q = 0; q < 4; q++) acc[i][j][q] = 0.f;

#pragma unroll
        for (int kk = 0; kk < 8; kk++) {
            const uint32_t ka = (uint32_t)(kk * 4096);
            uint32_t ah[4][4], bh[4][2];
#pragma unroll
            for (int mt = 0; mt < 4; mt++)
                ldm_x4t(ah[mt][0], ah[mt][2], ah[mt][1], ah[mt][3], sb + ka + aoffc[mt]);
#pragma unroll
            for (int pp = 0; pp < 2; pp++)
                ldm_x4t(bh[2 * pp][0], bh[2 * pp][1], bh[2 * pp + 1][0], bh[2 * pp + 1][1],
                        fj + ka + boffc[pp]);
            if (kk == 0 && it + 1 < 8)
                load_tile(sb + 32768u + (uint32_t)((it + 1) & 1) * 32768u, (it + 1) * 128);
#pragma unroll
            for (int mt = 0; mt < 4; mt++)
#pragma unroll
                for (int nt = 0; nt < 4; nt++)
                    mma16816h(acc[mt][nt], ah[mt], bh[nt]);
        }

        const int j0 = it * 128;
#pragma unroll
        for (int nt = 0; nt < 4; nt++) {
            const int jc = j0 + wn + nt * 8 + 2 * tg;
            const float rn0 = g_RN[b * N_ + jc],     rn1 = g_RN[b * N_ + jc + 1];
            const float Tj0 = g_T [b * N_ + jc],     Tj1 = g_T [b * N_ + jc + 1];
#pragma unroll
            for (int mt = 0; mt < 4; mt++)
#pragma unroll
                for (int r = 0; r < 2; r++) {
                    float s0 = acc[mt][nt][r * 2 + 0] * rni[mt][r] * rn0;
                    float s1 = acc[mt][nt][r * 2 + 1] * rni[mt][r] * rn1;
                    float z0 = fmaf(0.5f * (Tii[mt][r] + Tj0), s0, burst_b);
                    float z1 = fmaf(0.5f * (Tii[mt][r] + Tj1), s1, burst_b);
                    rowp[mt][r] += fmaf(0.5f, tanh_fast(0.5f * z0), 0.5f);
                    rowp[mt][r] += fmaf(0.5f, tanh_fast(0.5f * z1), 0.5f);
                }
        }
    }

#pragma unroll
    for (int mt = 0; mt < 4; mt++)
#pragma unroll
        for (int r = 0; r < 2; r++) {
            float v = rowp[mt][r];
            v += __shfl_xor_sync(0xffffffffu, v, 1);
            v += __shfl_xor_sync(0xffffffffu, v, 2);
            if (tg == 0) rs[wm + mt * 16 + g + r * 8][w & 3] = v;
        }
    __syncthreads();
    if (t < 128) {
        float s = rs[t][0] + rs[t][1] + rs[t][2] + rs[t][3];
        float d = powf(s, burst_p);
        g_D[b * N_ + i0 + t] = fminf(fmaxf(d, 1e-3f), 1e3f);
    }
}

// ---------------- agg (split-K, deterministic; reads fp16 f) ----------------
__global__ __launch_bounds__(256) void k_agg(const float* __restrict__ lamp)
{
    const int b = blockIdx.y;
    const int part = blockIdx.x;
    const int nbase = part * 128;
    const float lam = 1.f / (1.f + __expf(-(*lamp)));
    const float oml = 1.f - lam;
    __shared__ float Ft[128][33];
    __shared__ float Pt[64][33];
    const int t = threadIdx.x, tx = t & 15, ty = t >> 4;
    const __half* F = g_Fh + (size_t)b * L_ * N_;
    const float* P = g_P + (size_t)b * M_ * N_;

    float acc[8][4];
#pragma unroll
    for (int i = 0; i < 8; i++)
#pragma unroll
        for (int j = 0; j < 4; j++) acc[i][j] = 0.f;

    for (int tl = 0; tl < 4; tl++) {
        const int n0 = nbase + tl * 32;
        __syncthreads();
#pragma unroll
        for (int p = 0; p < 16; p++) {
            int idx = t + p * 256; int row = idx >> 5, c = idx & 31;
            Ft[row][c] = __half2float(F[(size_t)row * N_ + n0 + c]);
        }
#pragma unroll
        for (int p = 0; p < 8; p++) {
            int idx = t + p * 256; int row = idx >> 5, c = idx & 31;
            float d = g_D[b * N_ + n0 + c];
            Pt[row][c] = P[(size_t)row * N_ + n0 + c] * (oml + lam / (d + 1e-6f));
        }
        __syncthreads();
#pragma unroll
        for (int n = 0; n < 32; n++) {
            float a[8], pv[4];
#pragma unroll
            for (int i = 0; i < 8; i++) a[i] = Ft[ty * 8 + i][n];
#pragma unroll
            for (int j = 0; j < 4; j++) pv[j] = Pt[tx * 4 + j][n];
#pragma unroll
            for (int i = 0; i < 8; i++)
#pragma unroll
                for (int j = 0; j < 4; j++) acc[i][j] = fmaf(a[i], pv[j], acc[i][j]);
        }
    }
    float* O = g_aggp + ((size_t)b * 8 + part) * L_ * M_;
#pragma unroll
    for (int i = 0; i < 8; i++)
#pragma unroll
        for (int j = 0; j < 4; j++)
            O[(ty * 8 + i) * M_ + tx * 4 + j] = acc[i][j];
}

// ---------------- final reduce + normalize + concat ----------------
__global__ void k_final(float* __restrict__ out)
{
    const int b = blockIdx.x, t = threadIdx.x;
    __shared__ float sAgg[L_ * M_];
    __shared__ float cn[64], cr[64], red[256];
    __shared__ float sh_tn, sh_gn;

    for (int idx = t; idx < L_ * M_; idx += 256) {
        float s = 0.f;
#pragma unroll
        for (int p = 0; p < 8; p++) s += g_aggp[((size_t)b * 8 + p) * L_ * M_ + idx];
        sAgg[idx] = s;
    }
    __syncthreads();

    if (t < 64) {
        float ss = 0.f;
        for (int l = 0; l < L_; l++) { float vv = sAgg[l * M_ + t]; ss = fmaf(vv, vv, ss); }
        float nn2 = fmaxf(sqrtf(ss), 1e-12f);
        cn[t] = nn2;
        cr[t] = ss / (nn2 * nn2);
    }
    float tv = g_tok[b * G_ + t];
    red[t] = tv * tv;
    __syncthreads();
    for (int o = 128; o; o >>= 1) { if (t < o) red[t] += red[t + o]; __syncthreads(); }
    float tokss = red[0];
    __syncthreads();
    red[t] = (t < 64) ? cr[t] : 0.f;
    __syncthreads();
    for (int o = 128; o; o >>= 1) { if (t < o) red[t] += red[t + o]; __syncthreads(); }
    if (t == 0) {
        float tn = fmaxf(sqrtf(tokss), 1e-12f);
        float gss = tokss / (tn * tn) + red[0];
        sh_tn = tn;
        sh_gn = fmaxf(sqrtf(gss), 1e-12f);
    }
    __syncthreads();

    const int ob = b * (G_ + L_ * M_);
    out[ob + t] = tv / (sh_tn * sh_gn);
    const float invg = 1.f / sh_gn;
    for (int idx = t; idx < L_ * M_; idx += 256) {
        int mcol = idx & (M_ - 1);
        out[ob + G_ + idx] = sAgg[idx] * invg / cn[mcol];
    }
}

// ---------------- launch ----------------
extern "C" void kernel_launch(void* const* d_in, const int* in_sizes, int n_in,
                              void* d_out, int out_size)
{
    const float* x    = (const float*)d_in[0];
    const float* tt   = (const float*)d_in[1];
    const float* Wt1  = (const float*)d_in[2];
    const float* bt1  = (const float*)d_in[3];
    const float* Wt2  = (const float*)d_in[4];
    const float* bt2  = (const float*)d_in[5];
    const float* Wc1  = (const float*)d_in[6];
    const float* bc1  = (const float*)d_in[7];
    const float* Wc2  = (const float*)d_in[8];
    const float* bc2  = (const float*)d_in[9];
    const float* Ws1  = (const float*)d_in[10];
    const float* bs1  = (const float*)d_in[11];
    const float* Ws2  = (const float*)d_in[12];
    const float* bs2  = (const float*)d_in[13];
    const float* Wtp  = (const float*)d_in[14];
    const float* btp  = (const float*)d_in[15];
    const float* dust = (const float*)d_in[16];
    const float* bb   = (const float*)d_in[17];
    const float* bp   = (const float*)d_in[18];
    const float* ld   = (const float*)d_in[19];
    float* out = (float*)d_out;

    cudaFuncSetAttribute(k_hidden_mma, cudaFuncAttributeMaxDynamicSharedMemorySize, 3 * HSTG);
    cudaFuncSetAttribute(k_gemm2_mma,  cudaFuncAttributeMaxDynamicSharedMemorySize, 3 * G2STG);
    cudaFuncSetAttribute(k_burst_mma,  cudaFuncAttributeMaxDynamicSharedMemorySize, 98304);

    k_splitX<<<1024, 256>>>(x, (B_ * C_ * N_) / 4);
    k_splitW<<<296, 256>>>(Wc1, Ws1, Wc2, Ws2);
    k_tok1  <<<dim3(16, 64), 256>>>(tt, Wt1, bt1);
    k_tok2  <<<dim3(16, 32), 256>>>(Wt2, bt2);

    k_hidden_mma<<<dim3(8, 8, 16), 256, 3 * HSTG>>>(bc1, bs1);
    k_gemm2_mma <<<dim3(8, 3, 16), 128, 3 * G2STG>>>(bc2, bs2);
    k_sinkhorn<<<16, 1024>>>(dust);
    k_coln    <<<64, 256>>>(Wtp, btp);
    k_burst_mma<<<dim3(8, 16), 256, 98304>>>(bb, bp);
    k_agg     <<<dim3(8, 16), 256>>>(ld);
    k_final   <<<16, 256>>>(out);
}

// round 17
// speedup vs baseline: 2.3114x; 1.1905x over previous
#include <cuda_runtime.h>
#include <cuda_fp16.h>
#include <math.h>
#include <stdint.h>

#define B_   16
#define C_   1536
#define N_   1024
#define M_   64
#define L_   128
#define G_   256
#define HID_ 512

// ---------------- scratch (device globals) ----------------
static __device__ __half g_Xh[B_ * C_ * N_];      // x fp16
static __device__ __half g_Wh[1024 * C_];         // W1 fp16 (rows 0..511 Wc1, 512..1023 Ws1)
static __device__ __half g_W2h[192 * HID_];       // W2 fp16 (rows 0..127 Wc2, 128..191 Ws2)
static __device__ __half g_Hh[B_ * 1024 * N_];    // hidden fp16 (relu'd)
static __device__ __half g_Fh[B_ * L_ * N_];      // f fp16
static __device__ float g_P   [B_ * M_ * N_];
static __device__ float g_T   [B_ * N_];
static __device__ float g_RN  [B_ * N_];
static __device__ float g_D   [B_ * N_];
static __device__ float g_Ht  [B_ * HID_];
static __device__ float g_tok [B_ * G_];
static __device__ float g_aggp[B_ * 8 * L_ * M_];

// ---------------- PTX helpers ----------------
__device__ __forceinline__ void ldm_x4(uint32_t &r0, uint32_t &r1, uint32_t &r2, uint32_t &r3, uint32_t addr) {
    asm volatile("ldmatrix.sync.aligned.m8n8.x4.shared.b16 {%0,%1,%2,%3}, [%4];"
                 : "=r"(r0), "=r"(r1), "=r"(r2), "=r"(r3) : "r"(addr));
}
__device__ __forceinline__ void ldm_x4t(uint32_t &r0, uint32_t &r1, uint32_t &r2, uint32_t &r3, uint32_t addr) {
    asm volatile("ldmatrix.sync.aligned.m8n8.x4.trans.shared.b16 {%0,%1,%2,%3}, [%4];"
                 : "=r"(r0), "=r"(r1), "=r"(r2), "=r"(r3) : "r"(addr));
}
__device__ __forceinline__ void mma16816h(float* c, const uint32_t* a, const uint32_t* b) {
    asm volatile("mma.sync.aligned.m16n8k16.row.col.f32.f16.f16.f32 "
                 "{%0,%1,%2,%3},{%4,%5,%6,%7},{%8,%9},{%0,%1,%2,%3};"
                 : "+f"(c[0]), "+f"(c[1]), "+f"(c[2]), "+f"(c[3])
                 : "r"(a[0]), "r"(a[1]), "r"(a[2]), "r"(a[3]), "r"(b[0]), "r"(b[1]));
}
__device__ __forceinline__ void cp16(uint32_t saddr, const void* gaddr) {
    asm volatile("cp.async.cg.shared.global [%0], [%1], 16;" :: "r"(saddr), "l"(gaddr));
}
#define CP_COMMIT() asm volatile("cp.async.commit_group;")
#define CP_WAIT(n)  asm volatile("cp.async.wait_group %0;" :: "n"(n))

__device__ __forceinline__ uint32_t smem_u32(const void* p) {
    uint32_t a;
    asm("{ .reg .u64 t; cvta.to.shared.u64 t, %1; cvt.u32.u64 %0, t; }" : "=r"(a) : "l"(p));
    return a;
}
__device__ __forceinline__ float tanh_fast(float x) {
    float r;
    asm("tanh.approx.f32 %0, %1;" : "=f"(r) : "f"(x));
    return r;
}

// ---------------- split X: fp32 -> fp16 ----------------
__global__ void k_splitX(const float* __restrict__ src, int n4)
{
    for (int i = blockIdx.x * blockDim.x + threadIdx.x; i < n4; i += gridDim.x * blockDim.x) {
        float4 v = reinterpret_cast<const float4*>(src)[i];
        __half2 ph0 = __halves2half2(__float2half_rn(v.x), __float2half_rn(v.y));
        __half2 ph1 = __halves2half2(__float2half_rn(v.z), __float2half_rn(v.w));
        uint2 uh = {*reinterpret_cast<uint32_t*>(&ph0), *reinterpret_cast<uint32_t*>(&ph1)};
        *reinterpret_cast<uint2*>(g_Xh + (size_t)i * 4) = uh;
    }
}

// ---------------- split ALL weights in one launch ----------------
__global__ void k_splitW(const float* __restrict__ Wc1, const float* __restrict__ Ws1,
                         const float* __restrict__ Wc2, const float* __restrict__ Ws2)
{
    const int r1 = (HID_ * C_) / 4;
    const int r2 = r1 + (HID_ * C_) / 4;
    const int r3 = r2 + (L_ * HID_) / 4;
    const int r4 = r3 + (M_ * HID_) / 4;
    for (int i = blockIdx.x * blockDim.x + threadIdx.x; i < r4; i += gridDim.x * blockDim.x) {
        const float* s;
        __half* d;
        int j;
        if (i < r1)      { s = Wc1; d = g_Wh;                       j = i; }
        else if (i < r2) { s = Ws1; d = g_Wh + (size_t)HID_ * C_;   j = i - r1; }
        else if (i < r3) { s = Wc2; d = g_W2h;                      j = i - r2; }
        else             { s = Ws2; d = g_W2h + (size_t)L_ * HID_;  j = i - r3; }
        float4 v = reinterpret_cast<const float4*>(s)[j];
        __half2 ph0 = __halves2half2(__float2half_rn(v.x), __float2half_rn(v.y));
        __half2 ph1 = __halves2half2(__float2half_rn(v.z), __float2half_rn(v.w));
        uint2 uh = {*reinterpret_cast<uint32_t*>(&ph0), *reinterpret_cast<uint32_t*>(&ph1)};
        *reinterpret_cast<uint2*>(d + (size_t)j * 4) = uh;
    }
}

// ---------------- big GEMM (pure fp16 HMMA): h = relu(W*x + b) ----------------
#define HSTG 32768u

__global__ __launch_bounds__(256, 2) void k_hidden_mma(
    const float* __restrict__ bc1, const float* __restrict__ bs1)
{
    extern __shared__ __align__(128) char dsm[];
    const uint32_t sb = smem_u32(dsm);
    const int t = threadIdx.x, w = t >> 5, lane = t & 31;
    const int wm = (w >> 2) * 64, wn = (w & 3) * 32;
    const int g = lane >> 2, tg = lane & 3;
    const int b = blockIdx.z, m0 = blockIdx.y * 128, n0 = blockIdx.x * 128;

    const __half* gWh = g_Wh + (size_t)m0 * C_;
    const __half* gXh = g_Xh + (size_t)b * C_ * N_ + n0;

    uint32_t a_so[4], b_so[4];
    size_t   a_go[4], b_go[4];
#pragma unroll
    for (int p = 0; p < 4; p++) {
        int id = t + p * 256;
        int am = id >> 3, ac = id & 7;
        a_so[p] = (uint32_t)(am * 128 + ((ac ^ (am & 7)) << 4));
        a_go[p] = (size_t)am * C_ + ac * 8;
        int bk = id >> 4, bc = id & 15;
        b_so[p] = 16384u + (uint32_t)(bk * 256 + ((bc ^ (bk & 7)) << 4));
        b_go[p] = (size_t)bk * N_ + bc * 8;
    }

    auto load_A = [&](uint32_t sd, int k0) {
#pragma unroll
        for (int p = 0; p < 4; p++) cp16(sd + a_so[p], gWh + k0 + a_go[p]);
    };
    auto load_B = [&](uint32_t sd, int k0) {
#pragma unroll
        for (int p = 0; p < 4; p++) cp16(sd + b_so[p], gXh + (size_t)k0 * N_ + b_go[p]);
        CP_COMMIT();
    };

    const int r15 = lane & 15, sel = lane >> 4;
    uint32_t aoff0[4], bb0[2];
#pragma unroll
    for (int mt = 0; mt < 4; mt++) {
        int m = wm + mt * 16 + r15;
        aoff0[mt] = (uint32_t)(m * 128 + ((sel ^ (m & 7)) << 4));
    }
#pragma unroll
    for (int pp = 0; pp < 2; pp++) {
        int cn = (w & 3) * 4 + 2 * pp + sel;
        bb0[pp] = 16384u + (uint32_t)(r15 * 256 + ((cn ^ (r15 & 7)) << 4));
    }

    float acc[4][4][4];
#pragma unroll
    for (int i = 0; i < 4; i++)
#pragma unroll
        for (int j = 0; j < 4; j++)
#pragma unroll
            for (int q = 0; q < 4; q++) acc[i][j][q] = 0.f;

    load_A(sb, 0);          load_B(sb, 0);
    load_A(sb + HSTG, 64);  load_B(sb + HSTG, 64);

    const int NIT = C_ / 64;   // 24
    for (int it = 0; it < NIT; it++) {
        if (it + 2 < NIT) { CP_WAIT(1); } else { CP_WAIT(0); }
        __syncthreads();
        const uint32_t sd = sb + (uint32_t)(it % 3) * HSTG;

#pragma unroll
        for (int s = 0; s < 4; s++) {
            uint32_t ah[4][4], bh[4][2];
            const uint32_t axr = (uint32_t)(s << 5);
            const uint32_t bof = (uint32_t)(s << 12);
#pragma unroll
            for (int mt = 0; mt < 4; mt++)
                ldm_x4(ah[mt][0], ah[mt][1], ah[mt][2], ah[mt][3], sd + (aoff0[mt] ^ axr));
#pragma unroll
            for (int pp = 0; pp < 2; pp++)
                ldm_x4t(bh[2 * pp][0], bh[2 * pp][1], bh[2 * pp + 1][0], bh[2 * pp + 1][1],
                        sd + bb0[pp] + bof);
            if (it + 2 < NIT) {
                if (s == 0) load_A(sb + (uint32_t)((it + 2) % 3) * HSTG, (it + 2) * 64);
                if (s == 1) load_B(sb + (uint32_t)((it + 2) % 3) * HSTG, (it + 2) * 64);
            }
#pragma unroll
            for (int mt = 0; mt < 4; mt++)
#pragma unroll
                for (int nt = 0; nt < 4; nt++)
                    mma16816h(acc[mt][nt], ah[mt], bh[nt]);
        }
    }

    const float* bptr = (m0 >= HID_) ? (bs1 - HID_) : bc1;
    __half* OH = g_Hh + (size_t)b * 1024 * N_;
#pragma unroll
    for (int mt = 0; mt < 4; mt++) {
        const int m = m0 + wm + mt * 16 + g;
        const float bv0 = bptr[m];
        const float bv1 = bptr[m + 8];
#pragma unroll
        for (int nt = 0; nt < 4; nt++) {
            const int n = n0 + wn + nt * 8 + 2 * tg;
#pragma unroll
            for (int rr = 0; rr < 2; rr++) {
                const int mm = m + rr * 8;
                const float bvv = rr ? bv1 : bv0;
                float v0 = fmaxf(acc[mt][nt][rr * 2 + 0] + bvv, 0.f);
                float v1 = fmaxf(acc[mt][nt][rr * 2 + 1] + bvv, 0.f);
                __half2 ph = __halves2half2(__float2half_rn(v0), __float2half_rn(v1));
                *reinterpret_cast<__half2*>(OH + (size_t)mm * N_ + n) = ph;
            }
        }
    }
}

// ---------------- second-layer GEMM (pure fp16 HMMA): f and p ----------------
#define G2STG 12288u

__global__ __launch_bounds__(128, 1) void k_gemm2_mma(
    const float* __restrict__ bc2, const float* __restrict__ bs2)
{
    extern __shared__ __align__(128) char dsm2[];
    const uint32_t sb = smem_u32(dsm2);
    const int t = threadIdx.x, w = t >> 5, lane = t & 31;
    const int wn = w * 32;
    const int g = lane >> 2, tg = lane & 3;
    const int b = blockIdx.z, mblk = blockIdx.y, n0 = blockIdx.x * 128;
    const int m0 = mblk * 64;
    const int koff = (mblk == 2) ? 512 : 0;

    const __half* gAh = g_W2h + (size_t)m0 * HID_;
    const __half* gBh = g_Hh + ((size_t)b * 1024 + koff) * N_ + n0;

    const int amA = t >> 2, acA = t & 3;
    const uint32_t a_s0 = 16u * (uint32_t)(amA * 4 + (acA ^ ((amA >> 1) & 3)));
    const uint32_t a_s1 = 16u * (uint32_t)((amA + 32) * 4 + (acA ^ (((amA + 32) >> 1) & 3)));
    const size_t a_g0 = (size_t)amA * HID_ + acA * 8;
    const size_t a_g1 = (size_t)(amA + 32) * HID_ + acA * 8;
    const int bkB = t >> 4, bcB = t & 15;
    uint32_t b_sl[4];
    size_t   b_gl[4];
#pragma unroll
    for (int p = 0; p < 4; p++) {
        int k = bkB + p * 8;
        b_sl[p] = 16u * (uint32_t)(k * 16 + (bcB ^ (k & 7)));
        b_gl[p] = (size_t)k * N_ + bcB * 8;
    }

    auto load_stage = [&](uint32_t sd, int k0) {
        cp16(sd + a_s0, gAh + k0 + a_g0);
        cp16(sd + a_s1, gAh + k0 + a_g1);
        const size_t kk = (size_t)k0 * N_;
#pragma unroll
        for (int p = 0; p < 4; p++)
            cp16(sd + 4096u + b_sl[p], gBh + kk + b_gl[p]);
        CP_COMMIT();
    };

    const int r15 = lane & 15, sel = lane >> 4;
    uint32_t aoff[2][4], bb0[2][2];
#pragma unroll
    for (int s = 0; s < 2; s++) {
#pragma unroll
        for (int mt = 0; mt < 4; mt++) {
            int m = mt * 16 + r15;
            int c = 2 * s + sel;
            aoff[s][mt] = 16u * (uint32_t)(m * 4 + (c ^ ((m >> 1) & 3)));
        }
        int k = s * 16 + r15;
#pragma unroll
        for (int pp = 0; pp < 2; pp++) {
            int cn = w * 4 + 2 * pp + sel;
            bb0[s][pp] = 16u * (uint32_t)(k * 16 + (cn ^ (k & 7)));
        }
    }

    float acc[4][4][4];
#pragma unroll
    for (int i = 0; i < 4; i++)
#pragma unroll
        for (int j = 0; j < 4; j++)
#pragma unroll
            for (int q = 0; q < 4; q++) acc[i][j][q] = 0.f;

    load_stage(sb, 0);
    load_stage(sb + G2STG, 32);

    const int NIT = HID_ / 32;   // 16
    for (int it = 0; it < NIT; it++) {
        if (it + 2 < NIT) { CP_WAIT(1); } else { CP_WAIT(0); }
        __syncthreads();
        const uint32_t sd = sb + (uint32_t)(it % 3) * G2STG;

#pragma unroll
        for (int s = 0; s < 2; s++) {
            uint32_t ah[4][4], bh[4][2];
#pragma unroll
            for (int mt = 0; mt < 4; mt++)
                ldm_x4(ah[mt][0], ah[mt][1], ah[mt][2], ah[mt][3], sd + aoff[s][mt]);
#pragma unroll
            for (int pp = 0; pp < 2; pp++)
                ldm_x4t(bh[2 * pp][0], bh[2 * pp][1], bh[2 * pp + 1][0], bh[2 * pp + 1][1],
                        sd + 4096u + bb0[s][pp]);
            if (s == 0 && it + 2 < NIT)
                load_stage(sb + (uint32_t)((it + 2) % 3) * G2STG, (it + 2) * 32);
#pragma unroll
            for (int mt = 0; mt < 4; mt++)
#pragma unroll
                for (int nt = 0; nt < 4; nt++)
                    mma16816h(acc[mt][nt], ah[mt], bh[nt]);
        }
    }

#pragma unroll
    for (int mt = 0; mt < 4; mt++) {
#pragma unroll
        for (int rr = 0; rr < 2; rr++) {
            const int gm = m0 + mt * 16 + g + rr * 8;
            const float bv = (gm < 128) ? bc2[gm] : bs2[gm - 128];
#pragma unroll
            for (int nt = 0; nt < 4; nt++) {
                const int n = n0 + wn + nt * 8 + 2 * tg;
                float v0 = acc[mt][nt][rr * 2 + 0] + bv;
                float v1 = acc[mt][nt][rr * 2 + 1] + bv;
                if (gm < 128) {
                    __half2 ph = __halves2half2(__float2half_rn(v0), __float2half_rn(v1));
                    *reinterpret_cast<__half2*>(g_Fh + (size_t)b * L_ * N_ + (size_t)gm * N_ + n) = ph;
                } else {
                    float2 v = {v0, v1};
                    *reinterpret_cast<float2*>(g_P + (size_t)b * M_ * N_ + (size_t)(gm - 128) * N_ + n) = v;
                }
            }
        }
    }
}

// ---------------- token MLP (warp-per-output) ----------------
__global__ void k_tok1(const float* __restrict__ t_in, const float* __restrict__ Wt1,
                       const float* __restrict__ bt1)
{
    const int b = blockIdx.x;
    const int w = threadIdx.x >> 5, lane = threadIdx.x & 31;
    const int m = blockIdx.y * 8 + w;
    const float* a = Wt1 + (size_t)m * C_;
    const float* v = t_in + (size_t)b * C_;
    float s = 0.f;
    for (int k = lane; k < C_; k += 32) s = fmaf(a[k], v[k], s);
#pragma unroll
    for (int o = 16; o; o >>= 1) s += __shfl_xor_sync(0xffffffffu, s, o);
    if (lane == 0) g_Ht[b * HID_ + m] = fmaxf(s + bt1[m], 0.f);
}

__global__ void k_tok2(const float* __restrict__ Wt2, const float* __restrict__ bt2)
{
    const int b = blockIdx.x;
    const int w = threadIdx.x >> 5, lane = threadIdx.x & 31;
    const int m = blockIdx.y * 8 + w;
    const float* a = Wt2 + (size_t)m * HID_;
    const float* v = g_Ht + (size_t)b * HID_;
    float s = 0.f;
    for (int k = lane; k < HID_; k += 32) s = fmaf(a[k], v[k], s);
#pragma unroll
    for (int o = 16; o; o >>= 1) s += __shfl_xor_sync(0xffffffffu, s, o);
    if (lane == 0) g_tok[b * G_ + m] = s + bt2[m];
}

// ---------------- Sinkhorn OT (3 iters) + exp, in place on g_P ----------------
__global__ void k_sinkhorn(const float* __restrict__ dust)
{
    const int b = blockIdx.x;
    const int tid = threadIdx.x;
    const float alpha = *dust;
    const float nrm = -logf((float)(M_ + N_));
    __shared__ float u[M_ + 1];
    __shared__ float v[N_];
    float* S = g_P + (size_t)b * M_ * N_;
    v[tid] = 0.f;
    __syncthreads();
    const int warp = tid >> 5, lane = tid & 31;

    for (int it = 0; it < 3; it++) {
        for (int r = warp; r <= M_; r += 32) {
            float mx = -3.4e38f;
            if (r < M_) { for (int n = lane; n < N_; n += 32) mx = fmaxf(mx, S[r * N_ + n] + v[n]); }
            else        { for (int n = lane; n < N_; n += 32) mx = fmaxf(mx, alpha + v[n]); }
#pragma unroll
            for (int o = 16; o; o >>= 1) mx = fmaxf(mx, __shfl_xor_sync(0xffffffffu, mx, o));
            float s = 0.f;
            if (r < M_) { for (int n = lane; n < N_; n += 32) s += __expf(S[r * N_ + n] + v[n] - mx); }
            else        { for (int n = lane; n < N_; n += 32) s += __expf(alpha + v[n] - mx); }
#pragma unroll
            for (int o = 16; o; o >>= 1) s += __shfl_xor_sync(0xffffffffu, s, o);
            if (lane == 0) {
                float lmu = (r < M_) ? nrm : (__logf((float)N_) + nrm);
                u[r] = lmu - (mx + __logf(s));
            }
        }
        __syncthreads();
        {
            const int n = tid;
            float mx = alpha + u[M_];
            for (int r = 0; r < M_; r++) mx = fmaxf(mx, S[r * N_ + n] + u[r]);
            float s = __expf(alpha + u[M_] - mx);
            for (int r = 0; r < M_; r++) s += __expf(S[r * N_ + n] + u[r] - mx);
            v[n] = nrm - (mx + __logf(s));
        }
        __syncthreads();
    }
    for (int idx = tid; idx < M_ * N_; idx += 1024) {
        int r = idx >> 10, n = idx & (N_ - 1);
        S[idx] = __expf(S[idx] + u[r] + v[n] - nrm);
    }
}

// ---------------- per-pixel column norm of f + temperature T ----------------
__global__ void k_coln(const float* __restrict__ Wtp, const float* __restrict__ btp)
{
    __shared__ float sw[L_];
    if (threadIdx.x < L_) sw[threadIdx.x] = Wtp[threadIdx.x];
    __syncthreads();
    const int pid = blockIdx.x * blockDim.x + threadIdx.x;
    const int b = pid >> 10, n = pid & 1023;
    const __half* F = g_Fh + (size_t)b * L_ * N_ + n;
    float ss = 0.f, tp = 0.f;
#pragma unroll 4
    for (int l = 0; l < L_; l++) {
        float vv = __half2float(F[(size_t)l * N_]);
        ss = fmaf(vv, vv, ss);
        tp = fmaf(vv, sw[l], tp);
    }
    g_RN[pid] = 1.f / fmaxf(sqrtf(ss), 1e-12f);
    float xx = tp + *btp;
    g_T[pid] = __logf(1.f + __expf(-fabsf(xx))) + fmaxf(xx, 0.f);
}

// ---------------- burst (pure fp16 HMMA gram): fused sigmoid rowsum ----------------
__global__ __launch_bounds__(256, 2) void k_burst_mma(const float* __restrict__ bbp,
                                                      const float* __restrict__ bpp)
{
    extern __shared__ __align__(128) char dsmb[];
    const uint32_t sb = smem_u32(dsmb);
    __shared__ float rs[128][4];
    const int t = threadIdx.x, w = t >> 5, lane = t & 31;
    const int wm = (w >> 2) * 64, wn = (w & 3) * 32;
    const int g = lane >> 2, tg = lane & 3;
    const int b = blockIdx.y, i0 = blockIdx.x * 128;
    const float burst_b = *bbp, burst_p = *bpp;

    const __half* Fh = g_Fh + (size_t)b * L_ * N_;

    auto load_tile = [&](uint32_t dst, int col0) {
#pragma unroll
        for (int p = 0; p < 8; p++) {
            int id = t + p * 256;
            int row = id >> 4, c = id & 15;
            uint32_t off = (uint32_t)(row * 256 + ((c ^ (row & 7)) << 4));
            cp16(dst + off, Fh + (size_t)row * N_ + col0 + c * 8);
        }
        CP_COMMIT();
    };

    const int r15 = lane & 15, sel = lane >> 4;
    uint32_t aoffc[4], boffc[2];
#pragma unroll
    for (int mt = 0; mt < 4; mt++) {
        int cm = ((wm + mt * 16) >> 3) + sel;
        aoffc[mt] = (uint32_t)(r15 * 256 + ((cm ^ (r15 & 7)) << 4));
    }
#pragma unroll
    for (int pp = 0; pp < 2; pp++) {
        int cj = (wn >> 3) + 2 * pp + sel;
        boffc[pp] = (uint32_t)(r15 * 256 + ((cj ^ (r15 & 7)) << 4));
    }

    float rni[4][2], Tii[4][2];
#pragma unroll
    for (int mt = 0; mt < 4; mt++)
#pragma unroll
        for (int r = 0; r < 2; r++) {
            int gi = i0 + wm + mt * 16 + g + r * 8;
            rni[mt][r] = g_RN[b * N_ + gi];
            Tii[mt][r] = g_T [b * N_ + gi];
        }

    float rowp[4][2];
#pragma unroll
    for (int mt = 0; mt < 4; mt++) { rowp[mt][0] = 0.f; rowp[mt][1] = 0.f; }

    load_tile(sb, i0);
    load_tile(sb + 32768u, 0);

    for (int it = 0; it < 8; it++) {
        CP_WAIT(0);
        __syncthreads();
        const uint32_t fj = sb + 32768u + (uint32_t)(it & 1) * 32768u;

        float acc[4][4][4];
#pragma unroll
        for (int i = 0; i < 4; i++)
#pragma unroll
            for (int j = 0; j < 4; j++)
#pragma unroll
                for (int q = 0; q < 4; q++) acc[i][j][q] = 0.f;

#pragma unroll
        for (int kk = 0; kk < 8; kk++) {
            const uint32_t ka = (uint32_t)(kk * 4096);
            uint32_t ah[4][4], bh[4][2];
#pragma unroll
            for (int mt = 0; mt < 4; mt++)
                ldm_x4t(ah[mt][0], ah[mt][2], ah[mt][1], ah[mt][3], sb + ka + aoffc[mt]);
#pragma unroll
            for (int pp = 0; pp < 2; pp++)
                ldm_x4t(bh[2 * pp][0], bh[2 * pp][1], bh[2 * pp + 1][0], bh[2 * pp + 1][1],
                        fj + ka + boffc[pp]);
            if (kk == 0 && it + 1 < 8)
                load_tile(sb + 32768u + (uint32_t)((it + 1) & 1) * 32768u, (it + 1) * 128);
#pragma unroll
            for (int mt = 0; mt < 4; mt++)
#pragma unroll
                for (int nt = 0; nt < 4; nt++)
                    mma16816h(acc[mt][nt], ah[mt], bh[nt]);
        }

        const int j0 = it * 128;
#pragma unroll
        for (int nt = 0; nt < 4; nt++) {
            const int jc = j0 + wn + nt * 8 + 2 * tg;
            const float rn0 = g_RN[b * N_ + jc],     rn1 = g_RN[b * N_ + jc + 1];
            const float Tj0 = g_T [b * N_ + jc],     Tj1 = g_T [b * N_ + jc + 1];
#pragma unroll
            for (int mt = 0; mt < 4; mt++)
#pragma unroll
                for (int r = 0; r < 2; r++) {
                    float s0 = acc[mt][nt][r * 2 + 0] * rni[mt][r] * rn0;
                    float s1 = acc[mt][nt][r * 2 + 1] * rni[mt][r] * rn1;
                    float z0 = fmaf(0.5f * (Tii[mt][r] + Tj0), s0, burst_b);
                    float z1 = fmaf(0.5f * (Tii[mt][r] + Tj1), s1, burst_b);
                    rowp[mt][r] += fmaf(0.5f, tanh_fast(0.5f * z0), 0.5f);
                    rowp[mt][r] += fmaf(0.5f, tanh_fast(0.5f * z1), 0.5f);
                }
        }
    }

#pragma unroll
    for (int mt = 0; mt < 4; mt++)
#pragma unroll
        for (int r = 0; r < 2; r++) {
            float v = rowp[mt][r];
            v += __shfl_xor_sync(0xffffffffu, v, 1);
            v += __shfl_xor_sync(0xffffffffu, v, 2);
            if (tg == 0) rs[wm + mt * 16 + g + r * 8][w & 3] = v;
        }
    __syncthreads();
    if (t < 128) {
        float s = rs[t][0] + rs[t][1] + rs[t][2] + rs[t][3];
        float d = powf(s, burst_p);
        g_D[b * N_ + i0 + t] = fminf(fmaxf(d, 1e-3f), 1e3f);
    }
}

// ---------------- agg (split-K, deterministic; reads fp16 f) ----------------
__global__ __launch_bounds__(256) void k_agg(const float* __restrict__ lamp)
{
    const int b = blockIdx.y;
    const int part = blockIdx.x;
    const int nbase = part * 128;
    const float lam = 1.f / (1.f + __expf(-(*lamp)));
    const float oml = 1.f - lam;
    __shared__ float Ft[128][33];
    __shared__ float Pt[64][33];
    const int t = threadIdx.x, tx = t & 15, ty = t >> 4;
    const __half* F = g_Fh + (size_t)b * L_ * N_;
    const float* P = g_P + (size_t)b * M_ * N_;

    float acc[8][4];
#pragma unroll
    for (int i = 0; i < 8; i++)
#pragma unroll
        for (int j = 0; j < 4; j++) acc[i][j] = 0.f;

    for (int tl = 0; tl < 4; tl++) {
        const int n0 = nbase + tl * 32;
        __syncthreads();
#pragma unroll
        for (int p = 0; p < 16; p++) {
            int idx = t + p * 256; int row = idx >> 5, c = idx & 31;
            Ft[row][c] = __half2float(F[(size_t)row * N_ + n0 + c]);
        }
#pragma unroll
        for (int p = 0; p < 8; p++) {
            int idx = t + p * 256; int row = idx >> 5, c = idx & 31;
            float d = g_D[b * N_ + n0 + c];
            Pt[row][c] = P[(size_t)row * N_ + n0 + c] * (oml + lam / (d + 1e-6f));
        }
        __syncthreads();
#pragma unroll
        for (int n = 0; n < 32; n++) {
            float a[8], pv[4];
#pragma unroll
            for (int i = 0; i < 8; i++) a[i] = Ft[ty * 8 + i][n];
#pragma unroll
            for (int j = 0; j < 4; j++) pv[j] = Pt[tx * 4 + j][n];
#pragma unroll
            for (int i = 0; i < 8; i++)
#pragma unroll
                for (int j = 0; j < 4; j++) acc[i][j] = fmaf(a[i], pv[j], acc[i][j]);
        }
    }
    float* O = g_aggp + ((size_t)b * 8 + part) * L_ * M_;
#pragma unroll
    for (int i = 0; i < 8; i++)
#pragma unroll
        for (int j = 0; j < 4; j++)
            O[(ty * 8 + i) * M_ + tx * 4 + j] = acc[i][j];
}

// ---------------- final reduce + normalize + concat ----------------
__global__ void k_final(float* __restrict__ out)
{
    const int b = blockIdx.x, t = threadIdx.x;
    __shared__ float sAgg[L_ * M_];
    __shared__ float cn[64], cr[64], red[256];
    __shared__ float sh_tn, sh_gn;

    for (int idx = t; idx < L_ * M_; idx += 256) {
        float s = 0.f;
#pragma unroll
        for (int p = 0; p < 8; p++) s += g_aggp[((size_t)b * 8 + p) * L_ * M_ + idx];
        sAgg[idx] = s;
    }
    __syncthreads();

    if (t < 64) {
        float ss = 0.f;
        for (int l = 0; l < L_; l++) { float vv = sAgg[l * M_ + t]; ss = fmaf(vv, vv, ss); }
        float nn2 = fmaxf(sqrtf(ss), 1e-12f);
        cn[t] = nn2;
        cr[t] = ss / (nn2 * nn2);
    }
    float tv = g_tok[b * G_ + t];
    red[t] = tv * tv;
    __syncthreads();
    for (int o = 128; o; o >>= 1) { if (t < o) red[t] += red[t + o]; __syncthreads(); }
    float tokss = red[0];
    __syncthreads();
    red[t] = (t < 64) ? cr[t] : 0.f;
    __syncthreads();
    for (int o = 128; o; o >>= 1) { if (t < o) red[t] += red[t + o]; __syncthreads(); }
    if (t == 0) {
        float tn = fmaxf(sqrtf(tokss), 1e-12f);
        float gss = tokss / (tn * tn) + red[0];
        sh_tn = tn;
        sh_gn = fmaxf(sqrtf(gss), 1e-12f);
    }
    __syncthreads();

    const int ob = b * (G_ + L_ * M_);
    out[ob + t] = tv / (sh_tn * sh_gn);
    const float invg = 1.f / sh_gn;
    for (int idx = t; idx < L_ * M_; idx += 256) {
        int mcol = idx & (M_ - 1);
        out[ob + G_ + idx] = sAgg[idx] * invg / cn[mcol];
    }
}

// ---------------- launch (stream-forked for graph parallelism) ----------------
extern "C" void kernel_launch(void* const* d_in, const int* in_sizes, int n_in,
                              void* d_out, int out_size)
{
    const float* x    = (const float*)d_in[0];
    const float* tt   = (const float*)d_in[1];
    const float* Wt1  = (const float*)d_in[2];
    const float* bt1  = (const float*)d_in[3];
    const float* Wt2  = (const float*)d_in[4];
    const float* bt2  = (const float*)d_in[5];
    const float* Wc1  = (const float*)d_in[6];
    const float* bc1  = (const float*)d_in[7];
    const float* Wc2  = (const float*)d_in[8];
    const float* bc2  = (const float*)d_in[9];
    const float* Ws1  = (const float*)d_in[10];
    const float* bs1  = (const float*)d_in[11];
    const float* Ws2  = (const float*)d_in[12];
    const float* bs2  = (const float*)d_in[13];
    const float* Wtp  = (const float*)d_in[14];
    const float* btp  = (const float*)d_in[15];
    const float* dust = (const float*)d_in[16];
    const float* bb   = (const float*)d_in[17];
    const float* bp   = (const float*)d_in[18];
    const float* ld   = (const float*)d_in[19];
    float* out = (float*)d_out;

    static cudaStream_t s2 = nullptr;
    static cudaEvent_t e0 = nullptr, e1 = nullptr, e2 = nullptr;
    if (s2 == nullptr) {
        cudaStreamCreateWithFlags(&s2, cudaStreamNonBlocking);
        cudaEventCreateWithFlags(&e0, cudaEventDisableTiming);
        cudaEventCreateWithFlags(&e1, cudaEventDisableTiming);
        cudaEventCreateWithFlags(&e2, cudaEventDisableTiming);
        cudaFuncSetAttribute(k_hidden_mma, cudaFuncAttributeMaxDynamicSharedMemorySize, 3 * HSTG);
        cudaFuncSetAttribute(k_gemm2_mma,  cudaFuncAttributeMaxDynamicSharedMemorySize, 3 * G2STG);
        cudaFuncSetAttribute(k_burst_mma,  cudaFuncAttributeMaxDynamicSharedMemorySize, 98304);
    }

    // fork: token MLP runs concurrently with split + hidden GEMM
    cudaEventRecord(e0, 0);
    cudaStreamWaitEvent(s2, e0, 0);
    k_tok1<<<dim3(16, 64), 256, 0, s2>>>(tt, Wt1, bt1);
    k_tok2<<<dim3(16, 32), 256, 0, s2>>>(Wt2, bt2);

    // main chain
    k_splitX<<<1024, 256>>>(x, (B_ * C_ * N_) / 4);
    k_splitW<<<296, 256>>>(Wc1, Ws1, Wc2, Ws2);
    k_hidden_mma<<<dim3(8, 8, 16), 256, 3 * HSTG>>>(bc1, bs1);
    k_gemm2_mma <<<dim3(8, 3, 16), 128, 3 * G2STG>>>(bc2, bs2);

    // fork: sinkhorn (needs P) concurrent with coln -> burst (need f)
    cudaEventRecord(e1, 0);
    cudaStreamWaitEvent(s2, e1, 0);
    k_sinkhorn<<<16, 1024, 0, s2>>>(dust);
    cudaEventRecord(e2, s2);

    k_coln    <<<64, 256>>>(Wtp, btp);
    k_burst_mma<<<dim3(8, 16), 256, 98304>>>(bb, bp);

    // join: agg needs P (s2) and D (main); tok already ordered before e2
    cudaStreamWaitEvent(0, e2, 0);
    k_agg  <<<dim3(8, 16), 256>>>(ld);
    k_final<<<16, 256>>>(out);
}